// round 2
// baseline (speedup 1.0000x reference)
#include <cuda_runtime.h>
#include <math.h>

// ---------------- compile-time capacity (N=50000, E=800000 per dataset) ----
#define N_MAX 50048
#define ET_MAX 852000

// ---------------- device scratch (allowed: __device__ globals) -------------
__device__ __align__(16) float g_h1  [(size_t)N_MAX * 256]; // x @ W1
__device__ __align__(16) float g_h1n [(size_t)N_MAX * 256]; // after agg1+LN+ReLU
__device__ __align__(16) float g_h2  [(size_t)N_MAX * 64];  // h1n @ W2
__device__ __align__(16) float g_alsrc1[(size_t)N_MAX * 4];
__device__ __align__(16) float g_aldst1[(size_t)N_MAX * 4];
__device__ __align__(16) float g_alsrc2[N_MAX];
__device__ __align__(16) float g_aldst2[N_MAX];
__device__ __align__(16) float g_ew1[(size_t)ET_MAX * 4];   // exp(leakyrelu(e)) per edge/head
__device__ __align__(16) float g_ew2[ET_MAX];
__device__ int g_deg[N_MAX + 1];
__device__ int g_rowptr[N_MAX + 1];
__device__ int g_wcur[N_MAX];
__device__ int g_esrc[ET_MAX];
__device__ int g_edst[ET_MAX];
__device__ int g_idx_is64;

// ---------------- edge-index dtype detection -------------------------------
// int64 little-endian indices < 2^31 have all-zero high 32-bit words.
__global__ void k_detect(const void* __restrict__ ei) {
    const unsigned int* p = (const unsigned int*)ei;
    int is64 = 1;
    for (int i = 0; i < 64; i++) {
        if (p[2 * i + 1] != 0u) { is64 = 0; break; }
    }
    g_idx_is64 = is64;
}

__device__ __forceinline__ int load_idx(const void* __restrict__ ei,
                                        long long pos, int is64, int N) {
    int v = is64 ? (int)((const long long*)ei)[pos]
                 : ((const int*)ei)[pos];
    // safety clamp: degrade to wrong-but-checkable instead of crashing
    v = v < 0 ? 0 : (v >= N ? N - 1 : v);
    return v;
}

// ---------------- CSR construction ----------------------------------------
__global__ void k_zero(int N) {
    int t = blockIdx.x * blockDim.x + threadIdx.x;
    if (t < N) g_deg[t] = 0;
}

__global__ void k_count(const void* __restrict__ ei, int E, int N) {
    int t = blockIdx.x * blockDim.x + threadIdx.x;
    int ET = E + N;
    if (t >= ET) return;
    int is64 = g_idx_is64;
    int dst = (t < E) ? load_idx(ei, (long long)E + t, is64, N) : (t - E);
    atomicAdd(&g_deg[dst], 1);
}

__global__ __launch_bounds__(1024) void k_scan(int N) {
    __shared__ int sh[1024];
    int tid = threadIdx.x;
    int carry = 0;
    if (tid == 0) g_rowptr[0] = 0;
    for (int base = 0; base < N; base += 1024) {
        int i = base + tid;
        int v = (i < N) ? g_deg[i] : 0;
        sh[tid] = v;
        __syncthreads();
        for (int off = 1; off < 1024; off <<= 1) {
            int tv = (tid >= off) ? sh[tid - off] : 0;
            __syncthreads();
            sh[tid] += tv;
            __syncthreads();
        }
        if (i < N) g_rowptr[i + 1] = carry + sh[tid];
        carry += sh[1023];
        __syncthreads();
    }
    for (int i = tid; i < N; i += 1024) g_wcur[i] = g_rowptr[i];
}

__global__ void k_scatter(const void* __restrict__ ei, int E, int N) {
    int t = blockIdx.x * blockDim.x + threadIdx.x;
    int ET = E + N;
    if (t >= ET) return;
    int is64 = g_idx_is64;
    int src, dst;
    if (t < E) {
        src = load_idx(ei, t, is64, N);
        dst = load_idx(ei, (long long)E + t, is64, N);
    } else {
        src = t - E; dst = t - E;
    }
    int pos = atomicAdd(&g_wcur[dst], 1);
    g_esrc[pos] = src;
    g_edst[pos] = dst;
}

// ---------------- fp32 tiled GEMM: C[M,Nt] = A[M,K] @ B[K,Nt] --------------
// BM=BN=64, BK=64, 256 threads, 4x4 micro-tile. K, Nt multiples of 64.
__global__ __launch_bounds__(256) void k_gemm(const float* __restrict__ A,
                                              const float* __restrict__ B,
                                              float* __restrict__ C,
                                              int M, int Nt, int K) {
    __shared__ float As[64][68]; // As[k][m]
    __shared__ float Bs[64][68]; // Bs[k][n]
    int m0 = blockIdx.x * 64, n0 = blockIdx.y * 64;
    int tid = threadIdx.x;
    int tx = tid & 15, ty = tid >> 4;
    float acc[4][4] = {};
    for (int kt = 0; kt < K; kt += 64) {
#pragma unroll
        for (int r = 0; r < 4; r++) {
            int idx = tid + r * 256;          // 0..1023
            int row = idx >> 4;               // 0..63
            int c4 = (idx & 15) * 4;          // 0..60
            float4 v = make_float4(0.f, 0.f, 0.f, 0.f);
            int gr = m0 + row;
            if (gr < M) v = *reinterpret_cast<const float4*>(A + (size_t)gr * K + kt + c4);
            As[c4 + 0][row] = v.x; As[c4 + 1][row] = v.y;
            As[c4 + 2][row] = v.z; As[c4 + 3][row] = v.w;
        }
#pragma unroll
        for (int r = 0; r < 4; r++) {
            int idx = tid + r * 256;
            int row = idx >> 4;
            int c4 = (idx & 15) * 4;
            float4 v = *reinterpret_cast<const float4*>(B + (size_t)(kt + row) * Nt + n0 + c4);
            *reinterpret_cast<float4*>(&Bs[row][c4]) = v;
        }
        __syncthreads();
#pragma unroll
        for (int kk = 0; kk < 64; kk++) {
            float4 a = *reinterpret_cast<const float4*>(&As[kk][ty * 4]);
            float4 b = *reinterpret_cast<const float4*>(&Bs[kk][tx * 4]);
            float av[4] = {a.x, a.y, a.z, a.w};
            float bv[4] = {b.x, b.y, b.z, b.w};
#pragma unroll
            for (int i = 0; i < 4; i++)
#pragma unroll
                for (int j = 0; j < 4; j++) acc[i][j] += av[i] * bv[j];
        }
        __syncthreads();
    }
#pragma unroll
    for (int i = 0; i < 4; i++) {
        int gr = m0 + ty * 4 + i;
        if (gr < M) {
            float4 v = make_float4(acc[i][0], acc[i][1], acc[i][2], acc[i][3]);
            *reinterpret_cast<float4*>(C + (size_t)gr * Nt + n0 + tx * 4) = v;
        }
    }
}

// ---------------- attention logits: al = sum_c h[n,hd,c] * a[hd,c] ---------
__global__ void k_al(const float* __restrict__ h, const float* __restrict__ asv,
                     const float* __restrict__ adv, float* __restrict__ alsrc,
                     float* __restrict__ aldst, int N, int H) {
    int gw = (blockIdx.x * blockDim.x + threadIdx.x) >> 5;
    int lane = threadIdx.x & 31;
    if (gw >= N * H) return;
    int n = gw / H, hd = gw - n * H;
    const float* row = h + ((size_t)n * H + hd) * 64;
    const float* a1 = asv + hd * 64;
    const float* a2 = adv + hd * 64;
    float v0 = row[lane], v1 = row[lane + 32];
    float s1 = v0 * a1[lane] + v1 * a1[lane + 32];
    float s2 = v0 * a2[lane] + v1 * a2[lane + 32];
#pragma unroll
    for (int off = 16; off; off >>= 1) {
        s1 += __shfl_down_sync(0xffffffffu, s1, off);
        s2 += __shfl_down_sync(0xffffffffu, s2, off);
    }
    if (lane == 0) { alsrc[gw] = s1; aldst[gw] = s2; }
}

__device__ __forceinline__ float lrelu(float x) { return x > 0.f ? x : 0.2f * x; }

// ---------------- per-edge softmax weights (unnormalized) ------------------
__global__ void k_ew1(int ET) {
    int t = blockIdx.x * blockDim.x + threadIdx.x;
    if (t >= ET * 4) return;
    int i = t >> 2, hd = t & 3;
    int s = g_esrc[i], d = g_edst[i];
    float e = g_alsrc1[s * 4 + hd] + g_aldst1[d * 4 + hd];
    g_ew1[t] = __expf(lrelu(e));
}

__global__ void k_ew2(int ET) {
    int t = blockIdx.x * blockDim.x + threadIdx.x;
    if (t >= ET) return;
    int s = g_esrc[t], d = g_edst[t];
    float e = g_alsrc2[s] + g_aldst2[d];
    g_ew2[t] = __expf(lrelu(e));
}

// ---------------- layer 1 aggregation + bias + LN(256) + ReLU --------------
// one 64-thread block per dst node; thread t owns channels [4t, 4t+4)
__global__ __launch_bounds__(64) void k_agg1(const float* __restrict__ b1,
                                             const float* __restrict__ lng,
                                             const float* __restrict__ lnb) {
    int d = blockIdx.x;
    int t = threadIdx.x;
    int hd = t >> 4; // 4 heads x 16 threads
    __shared__ int s_src[64];
    __shared__ float s_w[64 * 4];
    __shared__ float rs[2], rq[2];
    int beg = g_rowptr[d], end = g_rowptr[d + 1];
    float4 acc = make_float4(0.f, 0.f, 0.f, 0.f);
    float wsum = 0.f;
    for (int base = beg; base < end; base += 64) {
        int nE = min(64, end - base);
        if (t < nE) s_src[t] = g_esrc[base + t];
        for (int idx = t; idx < nE * 4; idx += 64) s_w[idx] = g_ew1[(size_t)base * 4 + idx];
        __syncthreads();
        for (int j = 0; j < nE; j++) {
            int s = s_src[j];
            float w = s_w[j * 4 + hd];
            float4 hv = *reinterpret_cast<const float4*>(g_h1 + (size_t)s * 256 + t * 4);
            acc.x += w * hv.x; acc.y += w * hv.y;
            acc.z += w * hv.z; acc.w += w * hv.w;
            wsum += w;
        }
        __syncthreads();
    }
    float inv = 1.f / wsum;
    float4 bv = *reinterpret_cast<const float4*>(b1 + t * 4);
    float4 o;
    o.x = acc.x * inv + bv.x; o.y = acc.y * inv + bv.y;
    o.z = acc.z * inv + bv.z; o.w = acc.w * inv + bv.w;
    // LayerNorm over 256 channels
    float s = o.x + o.y + o.z + o.w;
    float q = o.x * o.x + o.y * o.y + o.z * o.z + o.w * o.w;
#pragma unroll
    for (int off = 16; off; off >>= 1) {
        s += __shfl_xor_sync(0xffffffffu, s, off);
        q += __shfl_xor_sync(0xffffffffu, q, off);
    }
    if ((t & 31) == 0) { rs[t >> 5] = s; rq[t >> 5] = q; }
    __syncthreads();
    float S = rs[0] + rs[1], Q = rq[0] + rq[1];
    float mu = S * (1.f / 256.f);
    float var = Q * (1.f / 256.f) - mu * mu;
    float rstd = rsqrtf(var + 1e-5f);
    float4 gv = *reinterpret_cast<const float4*>(lng + t * 4);
    float4 nbv = *reinterpret_cast<const float4*>(lnb + t * 4);
    o.x = fmaxf((o.x - mu) * rstd * gv.x + nbv.x, 0.f);
    o.y = fmaxf((o.y - mu) * rstd * gv.y + nbv.y, 0.f);
    o.z = fmaxf((o.z - mu) * rstd * gv.z + nbv.z, 0.f);
    o.w = fmaxf((o.w - mu) * rstd * gv.w + nbv.w, 0.f);
    *reinterpret_cast<float4*>(g_h1n + (size_t)d * 256 + t * 4) = o;
}

// ---------------- layer 2 aggregation + LN(64) + ReLU + MLP head -----------
// one 64-thread block per dst; threads 0..15 do the gather (float4 each)
__global__ __launch_bounds__(64) void k_agg2(const float* __restrict__ b2,
                                             const float* __restrict__ lng,
                                             const float* __restrict__ lnb,
                                             const float* __restrict__ f1W,
                                             const float* __restrict__ f1b,
                                             const float* __restrict__ f2W,
                                             const float* __restrict__ f2b,
                                             float* __restrict__ out) {
    int d = blockIdx.x;
    int t = threadIdx.x;
    __shared__ int s_src[64];
    __shared__ float s_w[64];
    __shared__ __align__(16) float hn[64];
    int beg = g_rowptr[d], end = g_rowptr[d + 1];
    float4 acc = make_float4(0.f, 0.f, 0.f, 0.f);
    float wsum = 0.f;
    for (int base = beg; base < end; base += 64) {
        int nE = min(64, end - base);
        if (t < nE) { s_src[t] = g_esrc[base + t]; s_w[t] = g_ew2[base + t]; }
        __syncthreads();
        if (t < 16) {
            for (int j = 0; j < nE; j++) {
                int s = s_src[j];
                float w = s_w[j];
                float4 hv = *reinterpret_cast<const float4*>(g_h2 + (size_t)s * 64 + t * 4);
                acc.x += w * hv.x; acc.y += w * hv.y;
                acc.z += w * hv.z; acc.w += w * hv.w;
                wsum += w;
            }
        }
        __syncthreads();
    }
    if (t < 16) {
        float inv = 1.f / wsum;
        float4 bv = *reinterpret_cast<const float4*>(b2 + t * 4);
        float4 o;
        o.x = acc.x * inv + bv.x; o.y = acc.y * inv + bv.y;
        o.z = acc.z * inv + bv.z; o.w = acc.w * inv + bv.w;
        float s = o.x + o.y + o.z + o.w;
        float q = o.x * o.x + o.y * o.y + o.z * o.z + o.w * o.w;
#pragma unroll
        for (int off = 8; off; off >>= 1) {
            s += __shfl_xor_sync(0x0000ffffu, s, off);
            q += __shfl_xor_sync(0x0000ffffu, q, off);
        }
        float mu = s * (1.f / 64.f);
        float var = q * (1.f / 64.f) - mu * mu;
        float rstd = rsqrtf(var + 1e-5f);
        float4 gv = *reinterpret_cast<const float4*>(lng + t * 4);
        float4 nbv = *reinterpret_cast<const float4*>(lnb + t * 4);
        float4 y;
        y.x = fmaxf((o.x - mu) * rstd * gv.x + nbv.x, 0.f);
        y.y = fmaxf((o.y - mu) * rstd * gv.y + nbv.y, 0.f);
        y.z = fmaxf((o.z - mu) * rstd * gv.z + nbv.z, 0.f);
        y.w = fmaxf((o.w - mu) * rstd * gv.w + nbv.w, 0.f);
        *reinterpret_cast<float4*>(&hn[t * 4]) = y;
    }
    __syncthreads();
    // MLP head: 64 -> 32 (ReLU) -> 1
    if (t < 32) {
        float r = f1b[t];
#pragma unroll
        for (int k = 0; k < 64; k++) r += hn[k] * f1W[k * 32 + t];
        float v = fmaxf(r, 0.f) * f2W[t];
#pragma unroll
        for (int off = 16; off; off >>= 1) v += __shfl_down_sync(0xffffffffu, v, off);
        if (t == 0) out[d] = v + f2b[0];
    }
}

// ---------------- host launcher --------------------------------------------
extern "C" void kernel_launch(void* const* d_in, const int* in_sizes, int n_in,
                              void* d_out, int out_size) {
    const float* x       = (const float*)d_in[0];
    const void*  ei      = d_in[1];                 // int32 OR int64, auto-detected
    const float* W1      = (const float*)d_in[2];
    const float* as1     = (const float*)d_in[3];
    const float* ad1     = (const float*)d_in[4];
    const float* b1      = (const float*)d_in[5];
    const float* g1      = (const float*)d_in[6];
    const float* bb1     = (const float*)d_in[7];
    const float* W2      = (const float*)d_in[8];
    const float* as2     = (const float*)d_in[9];
    const float* ad2     = (const float*)d_in[10];
    const float* b2      = (const float*)d_in[11];
    const float* g2      = (const float*)d_in[12];
    const float* bb2     = (const float*)d_in[13];
    const float* f1W     = (const float*)d_in[14];
    const float* f1b     = (const float*)d_in[15];
    const float* f2W     = (const float*)d_in[16];
    const float* f2b     = (const float*)d_in[17];
    float* out = (float*)d_out;

    int N = in_sizes[0] / 128;
    int E = in_sizes[1] / 2;
    int ET = E + N;

    float *h1p, *h1np, *h2p, *als1p, *ald1p, *als2p, *ald2p;
    cudaGetSymbolAddress((void**)&h1p,   g_h1);
    cudaGetSymbolAddress((void**)&h1np,  g_h1n);
    cudaGetSymbolAddress((void**)&h2p,   g_h2);
    cudaGetSymbolAddress((void**)&als1p, g_alsrc1);
    cudaGetSymbolAddress((void**)&ald1p, g_aldst1);
    cudaGetSymbolAddress((void**)&als2p, g_alsrc2);
    cudaGetSymbolAddress((void**)&ald2p, g_aldst2);

    // CSR build (dst-sorted)
    k_detect <<<1, 1>>>(ei);
    k_zero   <<<(N + 255) / 256, 256>>>(N);
    k_count  <<<(ET + 255) / 256, 256>>>(ei, E, N);
    k_scan   <<<1, 1024>>>(N);
    k_scatter<<<(ET + 255) / 256, 256>>>(ei, E, N);

    // Layer 1
    k_gemm<<<dim3((N + 63) / 64, 4), 256>>>(x, W1, h1p, N, 256, 128);
    k_al  <<<(N * 4 + 7) / 8, 256>>>(h1p, as1, ad1, als1p, ald1p, N, 4);
    k_ew1 <<<(ET * 4 + 255) / 256, 256>>>(ET);
    k_agg1<<<N, 64>>>(b1, g1, bb1);

    // Layer 2
    k_gemm<<<dim3((N + 63) / 64, 1), 256>>>(h1np, W2, h2p, N, 64, 256);
    k_al  <<<(N + 7) / 8, 256>>>(h2p, as2, ad2, als2p, ald2p, N, 1);
    k_ew2 <<<(ET + 255) / 256, 256>>>(ET);
    k_agg2<<<N, 64>>>(b2, g2, bb2, f1W, f1b, f2W, f2b, out);

    (void)n_in; (void)out_size;
}

// round 3
// speedup vs baseline: 1.0388x; 1.0388x over previous
#include <cuda_runtime.h>
#include <math.h>

// ---------------- compile-time capacity (N=50000, E=800000 per dataset) ----
#define N_MAX 50048
#define ET_MAX 852000

// ---------------- device scratch (allowed: __device__ globals) -------------
__device__ __align__(16) float g_h1  [(size_t)N_MAX * 256]; // x @ W1
__device__ __align__(16) float g_h1n [(size_t)N_MAX * 256]; // after agg1+LN+ReLU
__device__ __align__(16) float g_h2  [(size_t)N_MAX * 64];  // h1n @ W2
__device__ __align__(16) float g_alsrc1[(size_t)N_MAX * 4];
__device__ __align__(16) float g_aldst1[(size_t)N_MAX * 4];
__device__ __align__(16) float g_alsrc2[N_MAX];
__device__ __align__(16) float g_aldst2[N_MAX];
__device__ int g_deg[N_MAX + 1];
__device__ int g_rowptr[N_MAX + 1];
__device__ int g_wcur[N_MAX];
__device__ int g_esrc[ET_MAX];
__device__ int g_idx_is64;

// ---------------- edge-index dtype detection -------------------------------
// int64 little-endian indices < 2^31 have all-zero high 32-bit words.
__global__ void k_detect(const void* __restrict__ ei) {
    const unsigned int* p = (const unsigned int*)ei;
    int is64 = 1;
    for (int i = 0; i < 64; i++) {
        if (p[2 * i + 1] != 0u) { is64 = 0; break; }
    }
    g_idx_is64 = is64;
}

__device__ __forceinline__ int load_idx(const void* __restrict__ ei,
                                        long long pos, int is64, int N) {
    int v = is64 ? (int)((const long long*)ei)[pos]
                 : ((const int*)ei)[pos];
    v = v < 0 ? 0 : (v >= N ? N - 1 : v);
    return v;
}

// ---------------- CSR construction ----------------------------------------
__global__ void k_zero(int N) {
    int t = blockIdx.x * blockDim.x + threadIdx.x;
    if (t < N) g_deg[t] = 0;
}

__global__ void k_count(const void* __restrict__ ei, int E, int N) {
    int t = blockIdx.x * blockDim.x + threadIdx.x;
    int ET = E + N;
    if (t >= ET) return;
    int is64 = g_idx_is64;
    int dst = (t < E) ? load_idx(ei, (long long)E + t, is64, N) : (t - E);
    atomicAdd(&g_deg[dst], 1);
}

// Fast single-block scan: each thread owns CH contiguous elements; two passes
// over g_deg (L1-resident on second pass), shuffle-based block scan between.
__global__ __launch_bounds__(1024) void k_scan(int N) {
    int tid = threadIdx.x;
    int lane = tid & 31, wid = tid >> 5;
    int CH = (N + 1023) >> 10;
    int base = tid * CH;
    // pass 1: per-thread total
    int sum = 0;
    for (int i = 0; i < CH; i++) {
        int idx = base + i;
        if (idx < N) sum += g_deg[idx];
    }
    // block-wide inclusive scan of per-thread sums
    int s = sum;
#pragma unroll
    for (int off = 1; off < 32; off <<= 1) {
        int v = __shfl_up_sync(0xffffffffu, s, off);
        if (lane >= off) s += v;
    }
    __shared__ int wsum[32];
    if (lane == 31) wsum[wid] = s;
    __syncthreads();
    if (wid == 0) {
        int w = wsum[lane];
#pragma unroll
        for (int off = 1; off < 32; off <<= 1) {
            int v = __shfl_up_sync(0xffffffffu, w, off);
            if (lane >= off) w += v;
        }
        wsum[lane] = w;
    }
    __syncthreads();
    int excl = s - sum + (wid ? wsum[wid - 1] : 0);
    // pass 2: re-read, emit exclusive prefixes
    int run = excl;
    for (int i = 0; i < CH; i++) {
        int idx = base + i;
        if (idx < N) {
            g_rowptr[idx] = run;
            g_wcur[idx] = run;
            run += g_deg[idx];
        }
    }
    if (tid == 1023) g_rowptr[N] = excl + sum;
}

__global__ void k_scatter(const void* __restrict__ ei, int E, int N) {
    int t = blockIdx.x * blockDim.x + threadIdx.x;
    int ET = E + N;
    if (t >= ET) return;
    int is64 = g_idx_is64;
    int src, dst;
    if (t < E) {
        src = load_idx(ei, t, is64, N);
        dst = load_idx(ei, (long long)E + t, is64, N);
    } else {
        src = t - E; dst = t - E;
    }
    int pos = atomicAdd(&g_wcur[dst], 1);
    g_esrc[pos] = src;
}

// ---------------- fp32 tiled GEMM: C[M,Nt] = A[M,K] @ B[K,Nt] --------------
__global__ __launch_bounds__(256) void k_gemm(const float* __restrict__ A,
                                              const float* __restrict__ B,
                                              float* __restrict__ C,
                                              int M, int Nt, int K) {
    __shared__ float As[64][68]; // As[k][m]
    __shared__ float Bs[64][68]; // Bs[k][n]
    int m0 = blockIdx.x * 64, n0 = blockIdx.y * 64;
    int tid = threadIdx.x;
    int tx = tid & 15, ty = tid >> 4;
    float acc[4][4] = {};
    for (int kt = 0; kt < K; kt += 64) {
#pragma unroll
        for (int r = 0; r < 4; r++) {
            int idx = tid + r * 256;
            int row = idx >> 4;
            int c4 = (idx & 15) * 4;
            float4 v = make_float4(0.f, 0.f, 0.f, 0.f);
            int gr = m0 + row;
            if (gr < M) v = *reinterpret_cast<const float4*>(A + (size_t)gr * K + kt + c4);
            As[c4 + 0][row] = v.x; As[c4 + 1][row] = v.y;
            As[c4 + 2][row] = v.z; As[c4 + 3][row] = v.w;
        }
#pragma unroll
        for (int r = 0; r < 4; r++) {
            int idx = tid + r * 256;
            int row = idx >> 4;
            int c4 = (idx & 15) * 4;
            float4 v = *reinterpret_cast<const float4*>(B + (size_t)(kt + row) * Nt + n0 + c4);
            *reinterpret_cast<float4*>(&Bs[row][c4]) = v;
        }
        __syncthreads();
#pragma unroll
        for (int kk = 0; kk < 64; kk++) {
            float4 a = *reinterpret_cast<const float4*>(&As[kk][ty * 4]);
            float4 b = *reinterpret_cast<const float4*>(&Bs[kk][tx * 4]);
            float av[4] = {a.x, a.y, a.z, a.w};
            float bv[4] = {b.x, b.y, b.z, b.w};
#pragma unroll
            for (int i = 0; i < 4; i++)
#pragma unroll
                for (int j = 0; j < 4; j++) acc[i][j] += av[i] * bv[j];
        }
        __syncthreads();
    }
#pragma unroll
    for (int i = 0; i < 4; i++) {
        int gr = m0 + ty * 4 + i;
        if (gr < M) {
            float4 v = make_float4(acc[i][0], acc[i][1], acc[i][2], acc[i][3]);
            *reinterpret_cast<float4*>(C + (size_t)gr * Nt + n0 + tx * 4) = v;
        }
    }
}

// ---------------- attention logits ----------------------------------------
__global__ void k_al(const float* __restrict__ h, const float* __restrict__ asv,
                     const float* __restrict__ adv, float* __restrict__ alsrc,
                     float* __restrict__ aldst, int N, int H) {
    int gw = (blockIdx.x * blockDim.x + threadIdx.x) >> 5;
    int lane = threadIdx.x & 31;
    if (gw >= N * H) return;
    int n = gw / H, hd = gw - n * H;
    const float* row = h + ((size_t)n * H + hd) * 64;
    const float* a1 = asv + hd * 64;
    const float* a2 = adv + hd * 64;
    float v0 = row[lane], v1 = row[lane + 32];
    float s1 = v0 * a1[lane] + v1 * a1[lane + 32];
    float s2 = v0 * a2[lane] + v1 * a2[lane + 32];
#pragma unroll
    for (int off = 16; off; off >>= 1) {
        s1 += __shfl_down_sync(0xffffffffu, s1, off);
        s2 += __shfl_down_sync(0xffffffffu, s2, off);
    }
    if (lane == 0) { alsrc[gw] = s1; aldst[gw] = s2; }
}

__device__ __forceinline__ float lrelu(float x) { return x > 0.f ? x : 0.2f * x; }

// ---------------- layer 1 aggregation + bias + LN(256) + ReLU --------------
// one 64-thread block per dst node; thread t owns channels [4t, 4t+4).
// edge weights computed inline (fused former k_ew1).
__global__ __launch_bounds__(64) void k_agg1(const float* __restrict__ b1,
                                             const float* __restrict__ lng,
                                             const float* __restrict__ lnb) {
    int d = blockIdx.x;
    int t = threadIdx.x;
    int hd = t >> 4; // 4 heads x 16 threads
    __shared__ int s_src[64];
    __shared__ float s_w[64 * 4];
    __shared__ float rs[2], rq[2];
    __shared__ float s_ad[4];
    if (t < 4) s_ad[t] = g_aldst1[d * 4 + t];
    int beg = g_rowptr[d], end = g_rowptr[d + 1];
    float4 acc = make_float4(0.f, 0.f, 0.f, 0.f);
    float wsum = 0.f;
    for (int base = beg; base < end; base += 64) {
        int nE = min(64, end - base);
        if (t < nE) s_src[t] = g_esrc[base + t];
        __syncthreads();
        for (int idx = t; idx < nE * 4; idx += 64) {
            int e = idx >> 2, h2 = idx & 3;
            float v = g_alsrc1[s_src[e] * 4 + h2] + s_ad[h2];
            s_w[idx] = __expf(lrelu(v));
        }
        __syncthreads();
        for (int j = 0; j < nE; j++) {
            int s = s_src[j];
            float w = s_w[j * 4 + hd];
            float4 hv = *reinterpret_cast<const float4*>(g_h1 + (size_t)s * 256 + t * 4);
            acc.x += w * hv.x; acc.y += w * hv.y;
            acc.z += w * hv.z; acc.w += w * hv.w;
            wsum += w;
        }
        __syncthreads();
    }
    float inv = 1.f / wsum;
    float4 bv = *reinterpret_cast<const float4*>(b1 + t * 4);
    float4 o;
    o.x = acc.x * inv + bv.x; o.y = acc.y * inv + bv.y;
    o.z = acc.z * inv + bv.z; o.w = acc.w * inv + bv.w;
    float s = o.x + o.y + o.z + o.w;
    float q = o.x * o.x + o.y * o.y + o.z * o.z + o.w * o.w;
#pragma unroll
    for (int off = 16; off; off >>= 1) {
        s += __shfl_xor_sync(0xffffffffu, s, off);
        q += __shfl_xor_sync(0xffffffffu, q, off);
    }
    if ((t & 31) == 0) { rs[t >> 5] = s; rq[t >> 5] = q; }
    __syncthreads();
    float S = rs[0] + rs[1], Q = rq[0] + rq[1];
    float mu = S * (1.f / 256.f);
    float var = Q * (1.f / 256.f) - mu * mu;
    float rstd = rsqrtf(var + 1e-5f);
    float4 gv = *reinterpret_cast<const float4*>(lng + t * 4);
    float4 nbv = *reinterpret_cast<const float4*>(lnb + t * 4);
    o.x = fmaxf((o.x - mu) * rstd * gv.x + nbv.x, 0.f);
    o.y = fmaxf((o.y - mu) * rstd * gv.y + nbv.y, 0.f);
    o.z = fmaxf((o.z - mu) * rstd * gv.z + nbv.z, 0.f);
    o.w = fmaxf((o.w - mu) * rstd * gv.w + nbv.w, 0.f);
    *reinterpret_cast<float4*>(g_h1n + (size_t)d * 256 + t * 4) = o;
}

// ---------------- layer 2 aggregation + LN(64) + ReLU + MLP head -----------
__global__ __launch_bounds__(64) void k_agg2(const float* __restrict__ b2,
                                             const float* __restrict__ lng,
                                             const float* __restrict__ lnb,
                                             const float* __restrict__ f1W,
                                             const float* __restrict__ f1b,
                                             const float* __restrict__ f2W,
                                             const float* __restrict__ f2b,
                                             float* __restrict__ out) {
    int d = blockIdx.x;
    int t = threadIdx.x;
    __shared__ int s_src[64];
    __shared__ float s_w[64];
    __shared__ __align__(16) float hn[64];
    int beg = g_rowptr[d], end = g_rowptr[d + 1];
    float ad2 = g_aldst2[d];
    float4 acc = make_float4(0.f, 0.f, 0.f, 0.f);
    float wsum = 0.f;
    for (int base = beg; base < end; base += 64) {
        int nE = min(64, end - base);
        if (t < nE) {
            int s = g_esrc[base + t];
            s_src[t] = s;
            s_w[t] = __expf(lrelu(g_alsrc2[s] + ad2));
        }
        __syncthreads();
        if (t < 16) {
            for (int j = 0; j < nE; j++) {
                int s = s_src[j];
                float w = s_w[j];
                float4 hv = *reinterpret_cast<const float4*>(g_h2 + (size_t)s * 64 + t * 4);
                acc.x += w * hv.x; acc.y += w * hv.y;
                acc.z += w * hv.z; acc.w += w * hv.w;
                wsum += w;
            }
        }
        __syncthreads();
    }
    if (t < 16) {
        float inv = 1.f / wsum;
        float4 bv = *reinterpret_cast<const float4*>(b2 + t * 4);
        float4 o;
        o.x = acc.x * inv + bv.x; o.y = acc.y * inv + bv.y;
        o.z = acc.z * inv + bv.z; o.w = acc.w * inv + bv.w;
        float s = o.x + o.y + o.z + o.w;
        float q = o.x * o.x + o.y * o.y + o.z * o.z + o.w * o.w;
#pragma unroll
        for (int off = 8; off; off >>= 1) {
            s += __shfl_xor_sync(0x0000ffffu, s, off);
            q += __shfl_xor_sync(0x0000ffffu, q, off);
        }
        float mu = s * (1.f / 64.f);
        float var = q * (1.f / 64.f) - mu * mu;
        float rstd = rsqrtf(var + 1e-5f);
        float4 gv = *reinterpret_cast<const float4*>(lng + t * 4);
        float4 nbv = *reinterpret_cast<const float4*>(lnb + t * 4);
        float4 y;
        y.x = fmaxf((o.x - mu) * rstd * gv.x + nbv.x, 0.f);
        y.y = fmaxf((o.y - mu) * rstd * gv.y + nbv.y, 0.f);
        y.z = fmaxf((o.z - mu) * rstd * gv.z + nbv.z, 0.f);
        y.w = fmaxf((o.w - mu) * rstd * gv.w + nbv.w, 0.f);
        *reinterpret_cast<float4*>(&hn[t * 4]) = y;
    }
    __syncthreads();
    if (t < 32) {
        float r = f1b[t];
#pragma unroll
        for (int k = 0; k < 64; k++) r += hn[k] * f1W[k * 32 + t];
        float v = fmaxf(r, 0.f) * f2W[t];
#pragma unroll
        for (int off = 16; off; off >>= 1) v += __shfl_down_sync(0xffffffffu, v, off);
        if (t == 0) out[d] = v + f2b[0];
    }
}

// ---------------- host launcher --------------------------------------------
extern "C" void kernel_launch(void* const* d_in, const int* in_sizes, int n_in,
                              void* d_out, int out_size) {
    const float* x       = (const float*)d_in[0];
    const void*  ei      = d_in[1];                 // int32 OR int64, auto-detected
    const float* W1      = (const float*)d_in[2];
    const float* as1     = (const float*)d_in[3];
    const float* ad1     = (const float*)d_in[4];
    const float* b1      = (const float*)d_in[5];
    const float* g1      = (const float*)d_in[6];
    const float* bb1     = (const float*)d_in[7];
    const float* W2      = (const float*)d_in[8];
    const float* as2     = (const float*)d_in[9];
    const float* ad2     = (const float*)d_in[10];
    const float* b2      = (const float*)d_in[11];
    const float* g2      = (const float*)d_in[12];
    const float* bb2     = (const float*)d_in[13];
    const float* f1W     = (const float*)d_in[14];
    const float* f1b     = (const float*)d_in[15];
    const float* f2W     = (const float*)d_in[16];
    const float* f2b     = (const float*)d_in[17];
    float* out = (float*)d_out;

    int N = in_sizes[0] / 128;
    int E = in_sizes[1] / 2;
    int ET = E + N;

    float *h1p, *h1np, *h2p, *als1p, *ald1p, *als2p, *ald2p;
    cudaGetSymbolAddress((void**)&h1p,   g_h1);
    cudaGetSymbolAddress((void**)&h1np,  g_h1n);
    cudaGetSymbolAddress((void**)&h2p,   g_h2);
    cudaGetSymbolAddress((void**)&als1p, g_alsrc1);
    cudaGetSymbolAddress((void**)&ald1p, g_aldst1);
    cudaGetSymbolAddress((void**)&als2p, g_alsrc2);
    cudaGetSymbolAddress((void**)&ald2p, g_aldst2);

    // CSR build (dst-sorted)
    k_detect <<<1, 1>>>(ei);
    k_zero   <<<(N + 255) / 256, 256>>>(N);
    k_count  <<<(ET + 255) / 256, 256>>>(ei, E, N);
    k_scan   <<<1, 1024>>>(N);
    k_scatter<<<(ET + 255) / 256, 256>>>(ei, E, N);

    // Layer 1
    k_gemm<<<dim3((N + 63) / 64, 4), 256>>>(x, W1, h1p, N, 256, 128);
    k_al  <<<(N * 4 + 7) / 8, 256>>>(h1p, as1, ad1, als1p, ald1p, N, 4);
    k_agg1<<<N, 64>>>(b1, g1, bb1);

    // Layer 2
    k_gemm<<<dim3((N + 63) / 64, 1), 256>>>(h1np, W2, h2p, N, 64, 256);
    k_al  <<<(N + 7) / 8, 256>>>(h2p, as2, ad2, als2p, ald2p, N, 1);
    k_agg2<<<N, 64>>>(b2, g2, bb2, f1W, f1b, f2W, f2b, out);

    (void)n_in; (void)out_size;
}

// round 7
// speedup vs baseline: 1.2496x; 1.2030x over previous
#include <cuda_runtime.h>
#include <math.h>

// ---------------- compile-time capacity (N=50000, E=800000 per dataset) ----
#define N_MAX 50048
#define ET_MAX 852000
#define SCAN_TILE 1024
#define NBLK_MAX 64

// ---------------- device scratch (allowed: __device__ globals) -------------
__device__ __align__(16) float g_h1  [(size_t)N_MAX * 256]; // x @ W1
__device__ __align__(16) float g_h1n [(size_t)N_MAX * 256]; // after agg1+LN+ReLU
__device__ __align__(16) float g_h2  [(size_t)N_MAX * 64];  // h1n @ W2
__device__ __align__(16) float g_alsrc1[(size_t)N_MAX * 4];
__device__ __align__(16) float g_aldst1[(size_t)N_MAX * 4];
__device__ __align__(16) float g_alsrc2[N_MAX];
__device__ __align__(16) float g_aldst2[N_MAX];
__device__ __align__(16) int g_deg[N_MAX + 4];
__device__ __align__(16) int g_rowptr[N_MAX + 4];
__device__ __align__(16) int g_wcur[N_MAX];
__device__ int g_esrc[ET_MAX];
__device__ int g_blksum[NBLK_MAX];
__device__ int g_idx_is64;

// ---------------- edge-index dtype detection -------------------------------
// int64 little-endian indices < 2^31 have all-zero high 32-bit words.
__global__ void k_detect(const void* __restrict__ ei) {
    const unsigned int* p = (const unsigned int*)ei;
    int is64 = 1;
    for (int i = 0; i < 64; i++) {
        if (p[2 * i + 1] != 0u) { is64 = 0; break; }
    }
    g_idx_is64 = is64;
}

__device__ __forceinline__ int load_idx(const void* __restrict__ ei,
                                        long long pos, int is64, int N) {
    int v = is64 ? (int)((const long long*)ei)[pos]
                 : ((const int*)ei)[pos];
    v = v < 0 ? 0 : (v >= N ? N - 1 : v);
    return v;
}

// ---------------- CSR construction ----------------------------------------
__global__ void k_zero(int N) {
    int t = blockIdx.x * blockDim.x + threadIdx.x;
    if (t < N) g_deg[t] = 0;
}

__global__ void k_count(const void* __restrict__ ei, int E, int N) {
    int t = blockIdx.x * blockDim.x + threadIdx.x;
    int ET = E + N;
    if (t >= ET) return;
    int is64 = g_idx_is64;
    int dst = (t < E) ? load_idx(ei, (long long)E + t, is64, N) : (t - E);
    atomicAdd(&g_deg[dst], 1);
}

// ---------------- 3-phase multi-block exclusive scan of g_deg --------------
__device__ __forceinline__ int4 load_deg4(int base, int N) {
    int4 v = make_int4(0, 0, 0, 0);
    if (base + 3 < N) {
        v = *reinterpret_cast<const int4*>(g_deg + base);
    } else {
        if (base + 0 < N) v.x = g_deg[base + 0];
        if (base + 1 < N) v.y = g_deg[base + 1];
        if (base + 2 < N) v.z = g_deg[base + 2];
        if (base + 3 < N) v.w = g_deg[base + 3];
    }
    return v;
}

__global__ __launch_bounds__(256) void k_scan1(int N) {
    int tid = threadIdx.x;
    int lane = tid & 31, wid = tid >> 5;
    int base = blockIdx.x * SCAN_TILE + tid * 4;
    int4 v = load_deg4(base, N);
    int s = v.x + v.y + v.z + v.w;
#pragma unroll
    for (int off = 16; off; off >>= 1) s += __shfl_xor_sync(0xffffffffu, s, off);
    __shared__ int ws[8];
    if (lane == 0) ws[wid] = s;
    __syncthreads();
    if (tid == 0) {
        int tot = 0;
#pragma unroll
        for (int i = 0; i < 8; i++) tot += ws[i];
        g_blksum[blockIdx.x] = tot;
    }
}

__global__ void k_scan2(int nblk, int N) {
    __shared__ int sh[NBLK_MAX];
    int tid = threadIdx.x;
    if (tid < nblk) sh[tid] = g_blksum[tid];
    __syncthreads();
    if (tid == 0) {
        int run = 0;
        for (int i = 0; i < nblk; i++) {
            int v = sh[i];
            sh[i] = run;
            run += v;
        }
        g_rowptr[N] = run;
    }
    __syncthreads();
    if (tid < nblk) g_blksum[tid] = sh[tid];
}

__global__ __launch_bounds__(256) void k_scan3(int N) {
    int tid = threadIdx.x;
    int lane = tid & 31, wid = tid >> 5;
    int base = blockIdx.x * SCAN_TILE + tid * 4;
    int4 v = load_deg4(base, N);
    int t1 = v.x, t2 = t1 + v.y, t3 = t2 + v.z, t4 = t3 + v.w;
    // block exclusive scan of per-thread sums t4
    int s = t4;
#pragma unroll
    for (int off = 1; off < 32; off <<= 1) {
        int u = __shfl_up_sync(0xffffffffu, s, off);
        if (lane >= off) s += u;
    }
    __shared__ int ws[8];
    if (lane == 31) ws[wid] = s;
    __syncthreads();
    if (wid == 0 && lane < 8) {
        int w = ws[lane];
#pragma unroll
        for (int off = 1; off < 8; off <<= 1) {
            int u = __shfl_up_sync(0x000000ffu, w, off);
            if (lane >= off) w += u;
        }
        ws[lane] = w;
    }
    __syncthreads();
    int excl = s - t4 + (wid ? ws[wid - 1] : 0);
    int off0 = g_blksum[blockIdx.x] + excl;
    if (base + 0 < N) { g_rowptr[base + 0] = off0;      g_wcur[base + 0] = off0; }
    if (base + 1 < N) { g_rowptr[base + 1] = off0 + t1; g_wcur[base + 1] = off0 + t1; }
    if (base + 2 < N) { g_rowptr[base + 2] = off0 + t2; g_wcur[base + 2] = off0 + t2; }
    if (base + 3 < N) { g_rowptr[base + 3] = off0 + t3; g_wcur[base + 3] = off0 + t3; }
}

__global__ void k_scatter(const void* __restrict__ ei, int E, int N) {
    int t = blockIdx.x * blockDim.x + threadIdx.x;
    int ET = E + N;
    if (t >= ET) return;
    int is64 = g_idx_is64;
    int src, dst;
    if (t < E) {
        src = load_idx(ei, t, is64, N);
        dst = load_idx(ei, (long long)E + t, is64, N);
    } else {
        src = t - E; dst = t - E;
    }
    int pos = atomicAdd(&g_wcur[dst], 1);
    g_esrc[pos] = src;
}

// ---------------- fp32 tiled GEMM: C[M,Nt] = A[M,K] @ B[K,Nt] --------------
__global__ __launch_bounds__(256) void k_gemm(const float* __restrict__ A,
                                              const float* __restrict__ B,
                                              float* __restrict__ C,
                                              int M, int Nt, int K) {
    __shared__ float As[64][68]; // As[k][m]
    __shared__ float Bs[64][68]; // Bs[k][n]
    int m0 = blockIdx.x * 64, n0 = blockIdx.y * 64;
    int tid = threadIdx.x;
    int tx = tid & 15, ty = tid >> 4;
    float acc[4][4] = {};
    for (int kt = 0; kt < K; kt += 64) {
#pragma unroll
        for (int r = 0; r < 4; r++) {
            int idx = tid + r * 256;
            int row = idx >> 4;
            int c4 = (idx & 15) * 4;
            float4 v = make_float4(0.f, 0.f, 0.f, 0.f);
            int gr = m0 + row;
            if (gr < M) v = *reinterpret_cast<const float4*>(A + (size_t)gr * K + kt + c4);
            As[c4 + 0][row] = v.x; As[c4 + 1][row] = v.y;
            As[c4 + 2][row] = v.z; As[c4 + 3][row] = v.w;
        }
#pragma unroll
        for (int r = 0; r < 4; r++) {
            int idx = tid + r * 256;
            int row = idx >> 4;
            int c4 = (idx & 15) * 4;
            float4 v = *reinterpret_cast<const float4*>(B + (size_t)(kt + row) * Nt + n0 + c4);
            *reinterpret_cast<float4*>(&Bs[row][c4]) = v;
        }
        __syncthreads();
#pragma unroll
        for (int kk = 0; kk < 64; kk++) {
            float4 a = *reinterpret_cast<const float4*>(&As[kk][ty * 4]);
            float4 b = *reinterpret_cast<const float4*>(&Bs[kk][tx * 4]);
            float av[4] = {a.x, a.y, a.z, a.w};
            float bv[4] = {b.x, b.y, b.z, b.w};
#pragma unroll
            for (int i = 0; i < 4; i++)
#pragma unroll
                for (int j = 0; j < 4; j++) acc[i][j] += av[i] * bv[j];
        }
        __syncthreads();
    }
#pragma unroll
    for (int i = 0; i < 4; i++) {
        int gr = m0 + ty * 4 + i;
        if (gr < M) {
            float4 v = make_float4(acc[i][0], acc[i][1], acc[i][2], acc[i][3]);
            *reinterpret_cast<float4*>(C + (size_t)gr * Nt + n0 + tx * 4) = v;
        }
    }
}

// ---------------- attention logits ----------------------------------------
__global__ void k_al(const float* __restrict__ h, const float* __restrict__ asv,
                     const float* __restrict__ adv, float* __restrict__ alsrc,
                     float* __restrict__ aldst, int N, int H) {
    int gw = (blockIdx.x * blockDim.x + threadIdx.x) >> 5;
    int lane = threadIdx.x & 31;
    if (gw >= N * H) return;
    int n = gw / H, hd = gw - n * H;
    const float* row = h + ((size_t)n * H + hd) * 64;
    const float* a1 = asv + hd * 64;
    const float* a2 = adv + hd * 64;
    float v0 = row[lane], v1 = row[lane + 32];
    float s1 = v0 * a1[lane] + v1 * a1[lane + 32];
    float s2 = v0 * a2[lane] + v1 * a2[lane + 32];
#pragma unroll
    for (int off = 16; off; off >>= 1) {
        s1 += __shfl_down_sync(0xffffffffu, s1, off);
        s2 += __shfl_down_sync(0xffffffffu, s2, off);
    }
    if (lane == 0) { alsrc[gw] = s1; aldst[gw] = s2; }
}

__device__ __forceinline__ float lrelu(float x) { return x > 0.f ? x : 0.2f * x; }

// ---------------- layer 1 aggregation + bias + LN(256) + ReLU --------------
__global__ __launch_bounds__(64) void k_agg1(const float* __restrict__ b1,
                                             const float* __restrict__ lng,
                                             const float* __restrict__ lnb) {
    int d = blockIdx.x;
    int t = threadIdx.x;
    int hd = t >> 4; // 4 heads x 16 threads
    __shared__ int s_src[64];
    __shared__ float s_w[64 * 4];
    __shared__ float rs[2], rq[2];
    __shared__ float s_ad[4];
    if (t < 4) s_ad[t] = g_aldst1[d * 4 + t];
    int beg = g_rowptr[d], end = g_rowptr[d + 1];
    float4 acc = make_float4(0.f, 0.f, 0.f, 0.f);
    float wsum = 0.f;
    for (int base = beg; base < end; base += 64) {
        int nE = min(64, end - base);
        if (t < nE) s_src[t] = g_esrc[base + t];
        __syncthreads();
        for (int idx = t; idx < nE * 4; idx += 64) {
            int e = idx >> 2, h2 = idx & 3;
            float v = g_alsrc1[s_src[e] * 4 + h2] + s_ad[h2];
            s_w[idx] = __expf(lrelu(v));
        }
        __syncthreads();
        for (int j = 0; j < nE; j++) {
            int s = s_src[j];
            float w = s_w[j * 4 + hd];
            float4 hv = *reinterpret_cast<const float4*>(g_h1 + (size_t)s * 256 + t * 4);
            acc.x += w * hv.x; acc.y += w * hv.y;
            acc.z += w * hv.z; acc.w += w * hv.w;
            wsum += w;
        }
        __syncthreads();
    }
    float inv = 1.f / wsum;
    float4 bv = *reinterpret_cast<const float4*>(b1 + t * 4);
    float4 o;
    o.x = acc.x * inv + bv.x; o.y = acc.y * inv + bv.y;
    o.z = acc.z * inv + bv.z; o.w = acc.w * inv + bv.w;
    float s = o.x + o.y + o.z + o.w;
    float q = o.x * o.x + o.y * o.y + o.z * o.z + o.w * o.w;
#pragma unroll
    for (int off = 16; off; off >>= 1) {
        s += __shfl_xor_sync(0xffffffffu, s, off);
        q += __shfl_xor_sync(0xffffffffu, q, off);
    }
    if ((t & 31) == 0) { rs[t >> 5] = s; rq[t >> 5] = q; }
    __syncthreads();
    float S = rs[0] + rs[1], Q = rq[0] + rq[1];
    float mu = S * (1.f / 256.f);
    float var = Q * (1.f / 256.f) - mu * mu;
    float rstd = rsqrtf(var + 1e-5f);
    float4 gv = *reinterpret_cast<const float4*>(lng + t * 4);
    float4 nbv = *reinterpret_cast<const float4*>(lnb + t * 4);
    o.x = fmaxf((o.x - mu) * rstd * gv.x + nbv.x, 0.f);
    o.y = fmaxf((o.y - mu) * rstd * gv.y + nbv.y, 0.f);
    o.z = fmaxf((o.z - mu) * rstd * gv.z + nbv.z, 0.f);
    o.w = fmaxf((o.w - mu) * rstd * gv.w + nbv.w, 0.f);
    *reinterpret_cast<float4*>(g_h1n + (size_t)d * 256 + t * 4) = o;
}

// ---------------- layer 2 aggregation + LN(64) + ReLU + MLP head -----------
__global__ __launch_bounds__(64) void k_agg2(const float* __restrict__ b2,
                                             const float* __restrict__ lng,
                                             const float* __restrict__ lnb,
                                             const float* __restrict__ f1W,
                                             const float* __restrict__ f1b,
                                             const float* __restrict__ f2W,
                                             const float* __restrict__ f2b,
                                             float* __restrict__ out) {
    int d = blockIdx.x;
    int t = threadIdx.x;
    __shared__ int s_src[64];
    __shared__ float s_w[64];
    __shared__ __align__(16) float hn[64];
    int beg = g_rowptr[d], end = g_rowptr[d + 1];
    float ad2 = g_aldst2[d];
    float4 acc = make_float4(0.f, 0.f, 0.f, 0.f);
    float wsum = 0.f;
    for (int base = beg; base < end; base += 64) {
        int nE = min(64, end - base);
        if (t < nE) {
            int s = g_esrc[base + t];
            s_src[t] = s;
            s_w[t] = __expf(lrelu(g_alsrc2[s] + ad2));
        }
        __syncthreads();
        if (t < 16) {
            for (int j = 0; j < nE; j++) {
                int s = s_src[j];
                float w = s_w[j];
                float4 hv = *reinterpret_cast<const float4*>(g_h2 + (size_t)s * 64 + t * 4);
                acc.x += w * hv.x; acc.y += w * hv.y;
                acc.z += w * hv.z; acc.w += w * hv.w;
                wsum += w;
            }
        }
        __syncthreads();
    }
    if (t < 16) {
        float inv = 1.f / wsum;
        float4 bv = *reinterpret_cast<const float4*>(b2 + t * 4);
        float4 o;
        o.x = acc.x * inv + bv.x; o.y = acc.y * inv + bv.y;
        o.z = acc.z * inv + bv.z; o.w = acc.w * inv + bv.w;
        float s = o.x + o.y + o.z + o.w;
        float q = o.x * o.x + o.y * o.y + o.z * o.z + o.w * o.w;
#pragma unroll
        for (int off = 8; off; off >>= 1) {
            s += __shfl_xor_sync(0x0000ffffu, s, off);
            q += __shfl_xor_sync(0x0000ffffu, q, off);
        }
        float mu = s * (1.f / 64.f);
        float var = q * (1.f / 64.f) - mu * mu;
        float rstd = rsqrtf(var + 1e-5f);
        float4 gv = *reinterpret_cast<const float4*>(lng + t * 4);
        float4 nbv = *reinterpret_cast<const float4*>(lnb + t * 4);
        float4 y;
        y.x = fmaxf((o.x - mu) * rstd * gv.x + nbv.x, 0.f);
        y.y = fmaxf((o.y - mu) * rstd * gv.y + nbv.y, 0.f);
        y.z = fmaxf((o.z - mu) * rstd * gv.z + nbv.z, 0.f);
        y.w = fmaxf((o.w - mu) * rstd * gv.w + nbv.w, 0.f);
        *reinterpret_cast<float4*>(&hn[t * 4]) = y;
    }
    __syncthreads();
    if (t < 32) {
        float r = f1b[t];
#pragma unroll
        for (int k = 0; k < 64; k++) r += hn[k] * f1W[k * 32 + t];
        float v = fmaxf(r, 0.f) * f2W[t];
#pragma unroll
        for (int off = 16; off; off >>= 1) v += __shfl_down_sync(0xffffffffu, v, off);
        if (t == 0) out[d] = v + f2b[0];
    }
}

// ---------------- host launcher --------------------------------------------
extern "C" void kernel_launch(void* const* d_in, const int* in_sizes, int n_in,
                              void* d_out, int out_size) {
    const float* x       = (const float*)d_in[0];
    const void*  ei      = d_in[1];                 // int32 OR int64, auto-detected
    const float* W1      = (const float*)d_in[2];
    const float* as1     = (const float*)d_in[3];
    const float* ad1     = (const float*)d_in[4];
    const float* b1      = (const float*)d_in[5];
    const float* g1      = (const float*)d_in[6];
    const float* bb1     = (const float*)d_in[7];
    const float* W2      = (const float*)d_in[8];
    const float* as2     = (const float*)d_in[9];
    const float* ad2     = (const float*)d_in[10];
    const float* b2      = (const float*)d_in[11];
    const float* g2      = (const float*)d_in[12];
    const float* bb2     = (const float*)d_in[13];
    const float* f1W     = (const float*)d_in[14];
    const float* f1b     = (const float*)d_in[15];
    const float* f2W     = (const float*)d_in[16];
    const float* f2b     = (const float*)d_in[17];
    float* out = (float*)d_out;

    int N = in_sizes[0] / 128;
    int E = in_sizes[1] / 2;
    int ET = E + N;
    int nblk = (N + SCAN_TILE - 1) / SCAN_TILE;

    float *h1p, *h1np, *h2p, *als1p, *ald1p, *als2p, *ald2p;
    cudaGetSymbolAddress((void**)&h1p,   g_h1);
    cudaGetSymbolAddress((void**)&h1np,  g_h1n);
    cudaGetSymbolAddress((void**)&h2p,   g_h2);
    cudaGetSymbolAddress((void**)&als1p, g_alsrc1);
    cudaGetSymbolAddress((void**)&ald1p, g_aldst1);
    cudaGetSymbolAddress((void**)&als2p, g_alsrc2);
    cudaGetSymbolAddress((void**)&ald2p, g_aldst2);

    // CSR build (dst-sorted)
    k_detect <<<1, 1>>>(ei);
    k_zero   <<<(N + 255) / 256, 256>>>(N);
    k_count  <<<(ET + 255) / 256, 256>>>(ei, E, N);
    k_scan1  <<<nblk, 256>>>(N);
    k_scan2  <<<1, 64>>>(nblk, N);
    k_scan3  <<<nblk, 256>>>(N);
    k_scatter<<<(ET + 255) / 256, 256>>>(ei, E, N);

    // Layer 1
    k_gemm<<<dim3((N + 63) / 64, 4), 256>>>(x, W1, h1p, N, 256, 128);
    k_al  <<<(N * 4 + 7) / 8, 256>>>(h1p, as1, ad1, als1p, ald1p, N, 4);
    k_agg1<<<N, 64>>>(b1, g1, bb1);

    // Layer 2
    k_gemm<<<dim3((N + 63) / 64, 1), 256>>>(h1np, W2, h2p, N, 64, 256);
    k_al  <<<(N + 7) / 8, 256>>>(h2p, as2, ad2, als2p, ald2p, N, 1);
    k_agg2<<<N, 64>>>(b2, g2, bb2, f1W, f1b, f2W, f2b, out);

    (void)n_in; (void)out_size;
}

// round 8
// speedup vs baseline: 1.2976x; 1.0384x over previous
#include <cuda_runtime.h>
#include <cuda_fp16.h>
#include <math.h>

// ---------------- compile-time capacity (N=50000, E=800000 per dataset) ----
#define N_MAX 50048
#define ET_MAX 852000
#define SCAN_TILE 1024
#define NBLK_MAX 64

// ---------------- device scratch (allowed: __device__ globals) -------------
__device__ __align__(16) __half g_h1 [(size_t)N_MAX * 256]; // x @ W1 (fp16 gather table)
__device__ __align__(16) float g_h1n [(size_t)N_MAX * 256]; // after agg1+LN+ReLU (fp32)
__device__ __align__(16) __half g_h2 [(size_t)N_MAX * 64];  // h1n @ W2 (fp16 gather table)
__device__ __align__(16) float g_alsrc1[(size_t)N_MAX * 4];
__device__ __align__(16) float g_aldst1[(size_t)N_MAX * 4];
__device__ __align__(16) float g_alsrc2[N_MAX];
__device__ __align__(16) float g_aldst2[N_MAX];
__device__ __align__(16) int g_deg[N_MAX + 4];
__device__ __align__(16) int g_rowptr[N_MAX + 4];
__device__ __align__(16) int g_wcur[N_MAX];
__device__ int g_esrc[ET_MAX];
__device__ int g_blksum[NBLK_MAX];
__device__ int g_idx_is64;

// ---------------- edge-index dtype detection -------------------------------
__global__ void k_detect(const void* __restrict__ ei) {
    const unsigned int* p = (const unsigned int*)ei;
    int is64 = 1;
    for (int i = 0; i < 64; i++) {
        if (p[2 * i + 1] != 0u) { is64 = 0; break; }
    }
    g_idx_is64 = is64;
}

__device__ __forceinline__ int load_idx(const void* __restrict__ ei,
                                        long long pos, int is64, int N) {
    int v = is64 ? (int)((const long long*)ei)[pos]
                 : ((const int*)ei)[pos];
    v = v < 0 ? 0 : (v >= N ? N - 1 : v);
    return v;
}

// ---------------- CSR construction ----------------------------------------
__global__ void k_zero(int N) {
    int t = blockIdx.x * blockDim.x + threadIdx.x;
    if (t < N) g_deg[t] = 0;
}

__global__ void k_count(const void* __restrict__ ei, int E, int N) {
    int t = blockIdx.x * blockDim.x + threadIdx.x;
    int ET = E + N;
    if (t >= ET) return;
    int is64 = g_idx_is64;
    int dst = (t < E) ? load_idx(ei, (long long)E + t, is64, N) : (t - E);
    atomicAdd(&g_deg[dst], 1);
}

// ---------------- 3-phase multi-block exclusive scan of g_deg --------------
__device__ __forceinline__ int4 load_deg4(int base, int N) {
    int4 v = make_int4(0, 0, 0, 0);
    if (base + 3 < N) {
        v = *reinterpret_cast<const int4*>(g_deg + base);
    } else {
        if (base + 0 < N) v.x = g_deg[base + 0];
        if (base + 1 < N) v.y = g_deg[base + 1];
        if (base + 2 < N) v.z = g_deg[base + 2];
        if (base + 3 < N) v.w = g_deg[base + 3];
    }
    return v;
}

__global__ __launch_bounds__(256) void k_scan1(int N) {
    int tid = threadIdx.x;
    int lane = tid & 31, wid = tid >> 5;
    int base = blockIdx.x * SCAN_TILE + tid * 4;
    int4 v = load_deg4(base, N);
    int s = v.x + v.y + v.z + v.w;
#pragma unroll
    for (int off = 16; off; off >>= 1) s += __shfl_xor_sync(0xffffffffu, s, off);
    __shared__ int ws[8];
    if (lane == 0) ws[wid] = s;
    __syncthreads();
    if (tid == 0) {
        int tot = 0;
#pragma unroll
        for (int i = 0; i < 8; i++) tot += ws[i];
        g_blksum[blockIdx.x] = tot;
    }
}

__global__ void k_scan2(int nblk, int N) {
    __shared__ int sh[NBLK_MAX];
    int tid = threadIdx.x;
    if (tid < nblk) sh[tid] = g_blksum[tid];
    __syncthreads();
    if (tid == 0) {
        int run = 0;
        for (int i = 0; i < nblk; i++) {
            int v = sh[i];
            sh[i] = run;
            run += v;
        }
        g_rowptr[N] = run;
    }
    __syncthreads();
    if (tid < nblk) g_blksum[tid] = sh[tid];
}

__global__ __launch_bounds__(256) void k_scan3(int N) {
    int tid = threadIdx.x;
    int lane = tid & 31, wid = tid >> 5;
    int base = blockIdx.x * SCAN_TILE + tid * 4;
    int4 v = load_deg4(base, N);
    int t1 = v.x, t2 = t1 + v.y, t3 = t2 + v.z, t4 = t3 + v.w;
    int s = t4;
#pragma unroll
    for (int off = 1; off < 32; off <<= 1) {
        int u = __shfl_up_sync(0xffffffffu, s, off);
        if (lane >= off) s += u;
    }
    __shared__ int ws[8];
    if (lane == 31) ws[wid] = s;
    __syncthreads();
    if (wid == 0 && lane < 8) {
        int w = ws[lane];
#pragma unroll
        for (int off = 1; off < 8; off <<= 1) {
            int u = __shfl_up_sync(0x000000ffu, w, off);
            if (lane >= off) w += u;
        }
        ws[lane] = w;
    }
    __syncthreads();
    int excl = s - t4 + (wid ? ws[wid - 1] : 0);
    int off0 = g_blksum[blockIdx.x] + excl;
    if (base + 0 < N) { g_rowptr[base + 0] = off0;      g_wcur[base + 0] = off0; }
    if (base + 1 < N) { g_rowptr[base + 1] = off0 + t1; g_wcur[base + 1] = off0 + t1; }
    if (base + 2 < N) { g_rowptr[base + 2] = off0 + t2; g_wcur[base + 2] = off0 + t2; }
    if (base + 3 < N) { g_rowptr[base + 3] = off0 + t3; g_wcur[base + 3] = off0 + t3; }
}

__global__ void k_scatter(const void* __restrict__ ei, int E, int N) {
    int t = blockIdx.x * blockDim.x + threadIdx.x;
    int ET = E + N;
    if (t >= ET) return;
    int is64 = g_idx_is64;
    int src, dst;
    if (t < E) {
        src = load_idx(ei, t, is64, N);
        dst = load_idx(ei, (long long)E + t, is64, N);
    } else {
        src = t - E; dst = t - E;
    }
    int pos = atomicAdd(&g_wcur[dst], 1);
    g_esrc[pos] = src;
}

// ---------------- output stores: fp32 or fp16 ------------------------------
__device__ __forceinline__ void store4(float* p, float4 v) {
    *reinterpret_cast<float4*>(p) = v;
}
__device__ __forceinline__ void store4(__half* p, float4 v) {
    __half2 a = __floats2half2_rn(v.x, v.y);
    __half2 b = __floats2half2_rn(v.z, v.w);
    *reinterpret_cast<__half2*>(p) = a;
    *reinterpret_cast<__half2*>(p + 2) = b;
}

// ---------------- fp32 tiled GEMM: C[M,Nt] = A[M,K] @ B[K,Nt] --------------
template <typename OT>
__global__ __launch_bounds__(256) void k_gemm(const float* __restrict__ A,
                                              const float* __restrict__ B,
                                              OT* __restrict__ C,
                                              int M, int Nt, int K) {
    __shared__ float As[64][68]; // As[k][m]
    __shared__ float Bs[64][68]; // Bs[k][n]
    int m0 = blockIdx.x * 64, n0 = blockIdx.y * 64;
    int tid = threadIdx.x;
    int tx = tid & 15, ty = tid >> 4;
    float acc[4][4] = {};
    for (int kt = 0; kt < K; kt += 64) {
#pragma unroll
        for (int r = 0; r < 4; r++) {
            int idx = tid + r * 256;
            int row = idx >> 4;
            int c4 = (idx & 15) * 4;
            float4 v = make_float4(0.f, 0.f, 0.f, 0.f);
            int gr = m0 + row;
            if (gr < M) v = *reinterpret_cast<const float4*>(A + (size_t)gr * K + kt + c4);
            As[c4 + 0][row] = v.x; As[c4 + 1][row] = v.y;
            As[c4 + 2][row] = v.z; As[c4 + 3][row] = v.w;
        }
#pragma unroll
        for (int r = 0; r < 4; r++) {
            int idx = tid + r * 256;
            int row = idx >> 4;
            int c4 = (idx & 15) * 4;
            float4 v = *reinterpret_cast<const float4*>(B + (size_t)(kt + row) * Nt + n0 + c4);
            *reinterpret_cast<float4*>(&Bs[row][c4]) = v;
        }
        __syncthreads();
#pragma unroll
        for (int kk = 0; kk < 64; kk++) {
            float4 a = *reinterpret_cast<const float4*>(&As[kk][ty * 4]);
            float4 b = *reinterpret_cast<const float4*>(&Bs[kk][tx * 4]);
            float av[4] = {a.x, a.y, a.z, a.w};
            float bv[4] = {b.x, b.y, b.z, b.w};
#pragma unroll
            for (int i = 0; i < 4; i++)
#pragma unroll
                for (int j = 0; j < 4; j++) acc[i][j] += av[i] * bv[j];
        }
        __syncthreads();
    }
#pragma unroll
    for (int i = 0; i < 4; i++) {
        int gr = m0 + ty * 4 + i;
        if (gr < M) {
            float4 v = make_float4(acc[i][0], acc[i][1], acc[i][2], acc[i][3]);
            store4(C + (size_t)gr * Nt + n0 + tx * 4, v);
        }
    }
}

// ---------------- attention logits (reads fp16 h) ---------------------------
__global__ void k_al(const __half* __restrict__ h, const float* __restrict__ asv,
                     const float* __restrict__ adv, float* __restrict__ alsrc,
                     float* __restrict__ aldst, int N, int H) {
    int gw = (blockIdx.x * blockDim.x + threadIdx.x) >> 5;
    int lane = threadIdx.x & 31;
    if (gw >= N * H) return;
    int n = gw / H, hd = gw - n * H;
    const __half* row = h + ((size_t)n * H + hd) * 64;
    const float* a1 = asv + hd * 64;
    const float* a2 = adv + hd * 64;
    __half2 p = *reinterpret_cast<const __half2*>(row + lane * 2);
    float2 f = __half22float2(p);
    float s1 = f.x * a1[lane * 2] + f.y * a1[lane * 2 + 1];
    float s2 = f.x * a2[lane * 2] + f.y * a2[lane * 2 + 1];
#pragma unroll
    for (int off = 16; off; off >>= 1) {
        s1 += __shfl_down_sync(0xffffffffu, s1, off);
        s2 += __shfl_down_sync(0xffffffffu, s2, off);
    }
    if (lane == 0) { alsrc[gw] = s1; aldst[gw] = s2; }
}

__device__ __forceinline__ float lrelu(float x) { return x > 0.f ? x : 0.2f * x; }

// ---------------- layer 1 aggregation + bias + LN(256) + ReLU --------------
// one 64-thread block per dst node; thread t owns channels [4t, 4t+4).
__global__ __launch_bounds__(64) void k_agg1(const float* __restrict__ b1,
                                             const float* __restrict__ lng,
                                             const float* __restrict__ lnb) {
    int d = blockIdx.x;
    int t = threadIdx.x;
    int hd = t >> 4; // 4 heads x 16 threads
    __shared__ int s_src[64];
    __shared__ float s_w[64 * 4];
    __shared__ float rs[2], rq[2];
    __shared__ float s_ad[4];
    if (t < 4) s_ad[t] = g_aldst1[d * 4 + t];
    int beg = g_rowptr[d], end = g_rowptr[d + 1];
    float4 acc = make_float4(0.f, 0.f, 0.f, 0.f);
    float wsum = 0.f;
    for (int base = beg; base < end; base += 64) {
        int nE = min(64, end - base);
        if (t < nE) s_src[t] = g_esrc[base + t];
        __syncthreads();
        for (int idx = t; idx < nE * 4; idx += 64) {
            int e = idx >> 2, h2 = idx & 3;
            float v = g_alsrc1[s_src[e] * 4 + h2] + s_ad[h2];
            s_w[idx] = __expf(lrelu(v));
        }
        __syncthreads();
        for (int j = 0; j < nE; j++) {
            int s = s_src[j];
            float w = s_w[j * 4 + hd];
            uint2 u = *reinterpret_cast<const uint2*>(g_h1 + (size_t)s * 256 + t * 4);
            float2 f0 = __half22float2(*reinterpret_cast<__half2*>(&u.x));
            float2 f1 = __half22float2(*reinterpret_cast<__half2*>(&u.y));
            acc.x += w * f0.x; acc.y += w * f0.y;
            acc.z += w * f1.x; acc.w += w * f1.y;
            wsum += w;
        }
        __syncthreads();
    }
    float inv = 1.f / wsum;
    float4 bv = *reinterpret_cast<const float4*>(b1 + t * 4);
    float4 o;
    o.x = acc.x * inv + bv.x; o.y = acc.y * inv + bv.y;
    o.z = acc.z * inv + bv.z; o.w = acc.w * inv + bv.w;
    float s = o.x + o.y + o.z + o.w;
    float q = o.x * o.x + o.y * o.y + o.z * o.z + o.w * o.w;
#pragma unroll
    for (int off = 16; off; off >>= 1) {
        s += __shfl_xor_sync(0xffffffffu, s, off);
        q += __shfl_xor_sync(0xffffffffu, q, off);
    }
    if ((t & 31) == 0) { rs[t >> 5] = s; rq[t >> 5] = q; }
    __syncthreads();
    float S = rs[0] + rs[1], Q = rq[0] + rq[1];
    float mu = S * (1.f / 256.f);
    float var = Q * (1.f / 256.f) - mu * mu;
    float rstd = rsqrtf(var + 1e-5f);
    float4 gv = *reinterpret_cast<const float4*>(lng + t * 4);
    float4 nbv = *reinterpret_cast<const float4*>(lnb + t * 4);
    o.x = fmaxf((o.x - mu) * rstd * gv.x + nbv.x, 0.f);
    o.y = fmaxf((o.y - mu) * rstd * gv.y + nbv.y, 0.f);
    o.z = fmaxf((o.z - mu) * rstd * gv.z + nbv.z, 0.f);
    o.w = fmaxf((o.w - mu) * rstd * gv.w + nbv.w, 0.f);
    *reinterpret_cast<float4*>(g_h1n + (size_t)d * 256 + t * 4) = o;
}

// ---------------- layer 2 aggregation + LN(64) + ReLU + MLP head -----------
__global__ __launch_bounds__(64) void k_agg2(const float* __restrict__ b2,
                                             const float* __restrict__ lng,
                                             const float* __restrict__ lnb,
                                             const float* __restrict__ f1W,
                                             const float* __restrict__ f1b,
                                             const float* __restrict__ f2W,
                                             const float* __restrict__ f2b,
                                             float* __restrict__ out) {
    int d = blockIdx.x;
    int t = threadIdx.x;
    __shared__ int s_src[64];
    __shared__ float s_w[64];
    __shared__ __align__(16) float hn[64];
    int beg = g_rowptr[d], end = g_rowptr[d + 1];
    float ad2 = g_aldst2[d];
    float4 acc = make_float4(0.f, 0.f, 0.f, 0.f);
    float wsum = 0.f;
    for (int base = beg; base < end; base += 64) {
        int nE = min(64, end - base);
        if (t < nE) {
            int s = g_esrc[base + t];
            s_src[t] = s;
            s_w[t] = __expf(lrelu(g_alsrc2[s] + ad2));
        }
        __syncthreads();
        if (t < 16) {
            for (int j = 0; j < nE; j++) {
                int s = s_src[j];
                float w = s_w[j];
                uint2 u = *reinterpret_cast<const uint2*>(g_h2 + (size_t)s * 64 + t * 4);
                float2 f0 = __half22float2(*reinterpret_cast<__half2*>(&u.x));
                float2 f1 = __half22float2(*reinterpret_cast<__half2*>(&u.y));
                acc.x += w * f0.x; acc.y += w * f0.y;
                acc.z += w * f1.x; acc.w += w * f1.y;
                wsum += w;
            }
        }
        __syncthreads();
    }
    if (t < 16) {
        float inv = 1.f / wsum;
        float4 bv = *reinterpret_cast<const float4*>(b2 + t * 4);
        float4 o;
        o.x = acc.x * inv + bv.x; o.y = acc.y * inv + bv.y;
        o.z = acc.z * inv + bv.z; o.w = acc.w * inv + bv.w;
        float s = o.x + o.y + o.z + o.w;
        float q = o.x * o.x + o.y * o.y + o.z * o.z + o.w * o.w;
#pragma unroll
        for (int off = 8; off; off >>= 1) {
            s += __shfl_xor_sync(0x0000ffffu, s, off);
            q += __shfl_xor_sync(0x0000ffffu, q, off);
        }
        float mu = s * (1.f / 64.f);
        float var = q * (1.f / 64.f) - mu * mu;
        float rstd = rsqrtf(var + 1e-5f);
        float4 gv = *reinterpret_cast<const float4*>(lng + t * 4);
        float4 nbv = *reinterpret_cast<const float4*>(lnb + t * 4);
        float4 y;
        y.x = fmaxf((o.x - mu) * rstd * gv.x + nbv.x, 0.f);
        y.y = fmaxf((o.y - mu) * rstd * gv.y + nbv.y, 0.f);
        y.z = fmaxf((o.z - mu) * rstd * gv.z + nbv.z, 0.f);
        y.w = fmaxf((o.w - mu) * rstd * gv.w + nbv.w, 0.f);
        *reinterpret_cast<float4*>(&hn[t * 4]) = y;
    }
    __syncthreads();
    if (t < 32) {
        float r = f1b[t];
#pragma unroll
        for (int k = 0; k < 64; k++) r += hn[k] * f1W[k * 32 + t];
        float v = fmaxf(r, 0.f) * f2W[t];
#pragma unroll
        for (int off = 16; off; off >>= 1) v += __shfl_down_sync(0xffffffffu, v, off);
        if (t == 0) out[d] = v + f2b[0];
    }
}

// ---------------- host launcher --------------------------------------------
extern "C" void kernel_launch(void* const* d_in, const int* in_sizes, int n_in,
                              void* d_out, int out_size) {
    const float* x       = (const float*)d_in[0];
    const void*  ei      = d_in[1];                 // int32 OR int64, auto-detected
    const float* W1      = (const float*)d_in[2];
    const float* as1     = (const float*)d_in[3];
    const float* ad1     = (const float*)d_in[4];
    const float* b1      = (const float*)d_in[5];
    const float* g1      = (const float*)d_in[6];
    const float* bb1     = (const float*)d_in[7];
    const float* W2      = (const float*)d_in[8];
    const float* as2     = (const float*)d_in[9];
    const float* ad2     = (const float*)d_in[10];
    const float* b2      = (const float*)d_in[11];
    const float* g2      = (const float*)d_in[12];
    const float* bb2     = (const float*)d_in[13];
    const float* f1W     = (const float*)d_in[14];
    const float* f1b     = (const float*)d_in[15];
    const float* f2W     = (const float*)d_in[16];
    const float* f2b     = (const float*)d_in[17];
    float* out = (float*)d_out;

    int N = in_sizes[0] / 128;
    int E = in_sizes[1] / 2;
    int ET = E + N;
    int nblk = (N + SCAN_TILE - 1) / SCAN_TILE;

    __half *h1p, *h2p;
    float *h1np, *als1p, *ald1p, *als2p, *ald2p;
    cudaGetSymbolAddress((void**)&h1p,   g_h1);
    cudaGetSymbolAddress((void**)&h1np,  g_h1n);
    cudaGetSymbolAddress((void**)&h2p,   g_h2);
    cudaGetSymbolAddress((void**)&als1p, g_alsrc1);
    cudaGetSymbolAddress((void**)&ald1p, g_aldst1);
    cudaGetSymbolAddress((void**)&als2p, g_alsrc2);
    cudaGetSymbolAddress((void**)&ald2p, g_aldst2);

    // CSR build (dst-sorted)
    k_detect <<<1, 1>>>(ei);
    k_zero   <<<(N + 255) / 256, 256>>>(N);
    k_count  <<<(ET + 255) / 256, 256>>>(ei, E, N);
    k_scan1  <<<nblk, 256>>>(N);
    k_scan2  <<<1, 64>>>(nblk, N);
    k_scan3  <<<nblk, 256>>>(N);
    k_scatter<<<(ET + 255) / 256, 256>>>(ei, E, N);

    // Layer 1
    k_gemm<__half><<<dim3((N + 63) / 64, 4), 256>>>(x, W1, h1p, N, 256, 128);
    k_al  <<<(N * 4 + 7) / 8, 256>>>(h1p, as1, ad1, als1p, ald1p, N, 4);
    k_agg1<<<N, 64>>>(b1, g1, bb1);

    // Layer 2
    k_gemm<__half><<<dim3((N + 63) / 64, 1), 256>>>(h1np, W2, h2p, N, 64, 256);
    k_al  <<<(N + 7) / 8, 256>>>(h2p, as2, ad2, als2p, ald2p, N, 1);
    k_agg2<<<N, 64>>>(b2, g2, bb2, f1W, f1b, f2W, f2b, out);

    (void)n_in; (void)out_size;
}

// round 10
// speedup vs baseline: 1.6508x; 1.2722x over previous
#include <cuda_runtime.h>
#include <cuda_fp16.h>
#include <math.h>

// ---------------- compile-time capacity (N=50000, E=800000 per dataset) ----
#define N_MAX 50048
#define ET_MAX 852000
#define SCAN_TILE 1024
#define NBLK_MAX 64

// ---------------- device scratch (allowed: __device__ globals) -------------
__device__ __align__(16) __half g_h1 [(size_t)N_MAX * 256]; // x @ W1 (fp16 gather table)
__device__ __align__(16) float g_h1n [(size_t)N_MAX * 256]; // after agg1+LN+ReLU (fp32)
__device__ __align__(16) __half g_h2 [(size_t)N_MAX * 64];  // h1n @ W2 (fp16 gather table)
__device__ __align__(16) float g_alsrc1[(size_t)N_MAX * 4];
__device__ __align__(16) float g_aldst1[(size_t)N_MAX * 4];
__device__ __align__(16) float g_alsrc2[N_MAX];
__device__ __align__(16) float g_aldst2[N_MAX];
__device__ __align__(16) int g_deg[N_MAX + 4];
__device__ __align__(16) int g_rowptr[N_MAX + 4];
__device__ __align__(16) int g_wcur[N_MAX];
__device__ int g_esrc[ET_MAX];
__device__ int g_blksum[NBLK_MAX];
__device__ int g_idx_is64;

// ---------------- edge-index dtype detection -------------------------------
__global__ void k_detect(const void* __restrict__ ei) {
    const unsigned int* p = (const unsigned int*)ei;
    int is64 = 1;
    for (int i = 0; i < 64; i++) {
        if (p[2 * i + 1] != 0u) { is64 = 0; break; }
    }
    g_idx_is64 = is64;
}

__device__ __forceinline__ int load_idx(const void* __restrict__ ei,
                                        long long pos, int is64, int N) {
    int v = is64 ? (int)((const long long*)ei)[pos]
                 : ((const int*)ei)[pos];
    v = v < 0 ? 0 : (v >= N ? N - 1 : v);
    return v;
}

// ---------------- CSR construction ----------------------------------------
__global__ void k_zero(int N) {
    int t = blockIdx.x * blockDim.x + threadIdx.x;
    if (t < N) g_deg[t] = 0;
}

__global__ void k_count(const void* __restrict__ ei, int E, int N) {
    int t = blockIdx.x * blockDim.x + threadIdx.x;
    int ET = E + N;
    if (t >= ET) return;
    int is64 = g_idx_is64;
    int dst = (t < E) ? load_idx(ei, (long long)E + t, is64, N) : (t - E);
    atomicAdd(&g_deg[dst], 1);
}

// ---------------- 3-phase multi-block exclusive scan of g_deg --------------
__device__ __forceinline__ int4 load_deg4(int base, int N) {
    int4 v = make_int4(0, 0, 0, 0);
    if (base + 3 < N) {
        v = *reinterpret_cast<const int4*>(g_deg + base);
    } else {
        if (base + 0 < N) v.x = g_deg[base + 0];
        if (base + 1 < N) v.y = g_deg[base + 1];
        if (base + 2 < N) v.z = g_deg[base + 2];
        if (base + 3 < N) v.w = g_deg[base + 3];
    }
    return v;
}

__global__ __launch_bounds__(256) void k_scan1(int N) {
    int tid = threadIdx.x;
    int lane = tid & 31, wid = tid >> 5;
    int base = blockIdx.x * SCAN_TILE + tid * 4;
    int4 v = load_deg4(base, N);
    int s = v.x + v.y + v.z + v.w;
#pragma unroll
    for (int off = 16; off; off >>= 1) s += __shfl_xor_sync(0xffffffffu, s, off);
    __shared__ int ws[8];
    if (lane == 0) ws[wid] = s;
    __syncthreads();
    if (tid == 0) {
        int tot = 0;
#pragma unroll
        for (int i = 0; i < 8; i++) tot += ws[i];
        g_blksum[blockIdx.x] = tot;
    }
}

__global__ void k_scan2(int nblk, int N) {
    __shared__ int sh[NBLK_MAX];
    int tid = threadIdx.x;
    if (tid < nblk) sh[tid] = g_blksum[tid];
    __syncthreads();
    if (tid == 0) {
        int run = 0;
        for (int i = 0; i < nblk; i++) {
            int v = sh[i];
            sh[i] = run;
            run += v;
        }
        g_rowptr[N] = run;
    }
    __syncthreads();
    if (tid < nblk) g_blksum[tid] = sh[tid];
}

__global__ __launch_bounds__(256) void k_scan3(int N) {
    int tid = threadIdx.x;
    int lane = tid & 31, wid = tid >> 5;
    int base = blockIdx.x * SCAN_TILE + tid * 4;
    int4 v = load_deg4(base, N);
    int t1 = v.x, t2 = t1 + v.y, t3 = t2 + v.z, t4 = t3 + v.w;
    int s = t4;
#pragma unroll
    for (int off = 1; off < 32; off <<= 1) {
        int u = __shfl_up_sync(0xffffffffu, s, off);
        if (lane >= off) s += u;
    }
    __shared__ int ws[8];
    if (lane == 31) ws[wid] = s;
    __syncthreads();
    if (wid == 0 && lane < 8) {
        int w = ws[lane];
#pragma unroll
        for (int off = 1; off < 8; off <<= 1) {
            int u = __shfl_up_sync(0x000000ffu, w, off);
            if (lane >= off) w += u;
        }
        ws[lane] = w;
    }
    __syncthreads();
    int excl = s - t4 + (wid ? ws[wid - 1] : 0);
    int off0 = g_blksum[blockIdx.x] + excl;
    if (base + 0 < N) { g_rowptr[base + 0] = off0;      g_wcur[base + 0] = off0; }
    if (base + 1 < N) { g_rowptr[base + 1] = off0 + t1; g_wcur[base + 1] = off0 + t1; }
    if (base + 2 < N) { g_rowptr[base + 2] = off0 + t2; g_wcur[base + 2] = off0 + t2; }
    if (base + 3 < N) { g_rowptr[base + 3] = off0 + t3; g_wcur[base + 3] = off0 + t3; }
}

__global__ void k_scatter(const void* __restrict__ ei, int E, int N) {
    int t = blockIdx.x * blockDim.x + threadIdx.x;
    int ET = E + N;
    if (t >= ET) return;
    int is64 = g_idx_is64;
    int src, dst;
    if (t < E) {
        src = load_idx(ei, t, is64, N);
        dst = load_idx(ei, (long long)E + t, is64, N);
    } else {
        src = t - E; dst = t - E;
    }
    int pos = atomicAdd(&g_wcur[dst], 1);
    g_esrc[pos] = src;
}

// ---------------- output stores ---------------------------------------------
__device__ __forceinline__ void store2(float* p, float a, float b) {
    p[0] = a; p[1] = b;
}
__device__ __forceinline__ void store2(__half* p, float a, float b) {
    *reinterpret_cast<__half2*>(p) = __floats2half2_rn(a, b);
}

// ---------------- tensor-core GEMM: C[M,Nt] = A[M,K] @ B[K,Nt] --------------
// 64x64 block tile, 128 threads (4 warps), whole K staged in smem as fp16.
// As[m][k] and Bs[n][k] (k-contiguous), row stride K+8 halves (conflict-free).
// mma.sync.aligned.m16n8k16.row.col.f32.f16.f16.f32
template <typename OT>
__global__ __launch_bounds__(128) void k_gemm_mma(const float* __restrict__ A,
                                                  const float* __restrict__ B,
                                                  OT* __restrict__ C,
                                                  int M, int Nt, int K) {
    extern __shared__ __half smh[];
    int rs = K + 8;                 // halves per row
    __half* As = smh;               // 64 x rs
    __half* Bs = smh + 64 * rs;     // 64 x rs
    int tid = threadIdx.x;
    int warp = tid >> 5, lane = tid & 31;
    int m0 = blockIdx.x * 64, n0 = blockIdx.y * 64;

    // ---- load A tile (convert fp32->fp16) ----
    int kq4 = K >> 2; // float4 per row
    for (int id = tid; id < 64 * kq4; id += 128) {
        int row = id / kq4, kq = id - row * kq4;
        float4 v = make_float4(0.f, 0.f, 0.f, 0.f);
        int gr = m0 + row;
        if (gr < M) v = *reinterpret_cast<const float4*>(A + (size_t)gr * K + kq * 4);
        __half2 h0 = __floats2half2_rn(v.x, v.y);
        __half2 h1 = __floats2half2_rn(v.z, v.w);
        __half* dst = As + row * rs + kq * 4;
        *reinterpret_cast<__half2*>(dst) = h0;
        *reinterpret_cast<__half2*>(dst + 2) = h1;
    }
    // ---- load B tile transposed: Bs[n][k] = B[k][n0+n] ----
    for (int id = tid; id < K * 16; id += 128) {
        int k = id >> 4, nq = id & 15;
        float4 v = *reinterpret_cast<const float4*>(B + (size_t)k * Nt + n0 + nq * 4);
        Bs[(nq * 4 + 0) * rs + k] = __float2half_rn(v.x);
        Bs[(nq * 4 + 1) * rs + k] = __float2half_rn(v.y);
        Bs[(nq * 4 + 2) * rs + k] = __float2half_rn(v.z);
        Bs[(nq * 4 + 3) * rs + k] = __float2half_rn(v.w);
    }
    __syncthreads();

    int g = lane >> 2, tig = lane & 3;
    int rs32 = rs >> 1;
    const unsigned int* As32 = reinterpret_cast<const unsigned int*>(As);
    const unsigned int* Bs32 = reinterpret_cast<const unsigned int*>(Bs);
    int mrow = warp * 16 + g;

    float c[8][4];
#pragma unroll
    for (int i = 0; i < 8; i++)
#pragma unroll
        for (int j = 0; j < 4; j++) c[i][j] = 0.f;

    int nks = K >> 4;
    for (int ks = 0; ks < nks; ks++) {
        unsigned int a0 = As32[(size_t)mrow * rs32 + ks * 8 + tig];
        unsigned int a1 = As32[(size_t)(mrow + 8) * rs32 + ks * 8 + tig];
        unsigned int a2 = As32[(size_t)mrow * rs32 + ks * 8 + 4 + tig];
        unsigned int a3 = As32[(size_t)(mrow + 8) * rs32 + ks * 8 + 4 + tig];
#pragma unroll
        for (int nt = 0; nt < 8; nt++) {
            int n = nt * 8 + g;
            unsigned int b0 = Bs32[(size_t)n * rs32 + ks * 8 + tig];
            unsigned int b1 = Bs32[(size_t)n * rs32 + ks * 8 + 4 + tig];
            asm volatile(
                "mma.sync.aligned.m16n8k16.row.col.f32.f16.f16.f32 "
                "{%0,%1,%2,%3},{%4,%5,%6,%7},{%8,%9},{%0,%1,%2,%3};"
                : "+f"(c[nt][0]), "+f"(c[nt][1]), "+f"(c[nt][2]), "+f"(c[nt][3])
                : "r"(a0), "r"(a1), "r"(a2), "r"(a3), "r"(b0), "r"(b1));
        }
    }

    // ---- epilogue ----
    int gr0 = m0 + warp * 16 + g;
    int gr1 = gr0 + 8;
#pragma unroll
    for (int nt = 0; nt < 8; nt++) {
        int gc = n0 + nt * 8 + tig * 2;
        if (gr0 < M) store2(C + (size_t)gr0 * Nt + gc, c[nt][0], c[nt][1]);
        if (gr1 < M) store2(C + (size_t)gr1 * Nt + gc, c[nt][2], c[nt][3]);
    }
}

// ---------------- attention logits (reads fp16 h) ---------------------------
__global__ void k_al(const __half* __restrict__ h, const float* __restrict__ asv,
                     const float* __restrict__ adv, float* __restrict__ alsrc,
                     float* __restrict__ aldst, int N, int H) {
    int gw = (blockIdx.x * blockDim.x + threadIdx.x) >> 5;
    int lane = threadIdx.x & 31;
    if (gw >= N * H) return;
    int n = gw / H, hd = gw - n * H;
    const __half* row = h + ((size_t)n * H + hd) * 64;
    const float* a1 = asv + hd * 64;
    const float* a2 = adv + hd * 64;
    __half2 p = *reinterpret_cast<const __half2*>(row + lane * 2);
    float2 f = __half22float2(p);
    float s1 = f.x * a1[lane * 2] + f.y * a1[lane * 2 + 1];
    float s2 = f.x * a2[lane * 2] + f.y * a2[lane * 2 + 1];
#pragma unroll
    for (int off = 16; off; off >>= 1) {
        s1 += __shfl_down_sync(0xffffffffu, s1, off);
        s2 += __shfl_down_sync(0xffffffffu, s2, off);
    }
    if (lane == 0) { alsrc[gw] = s1; aldst[gw] = s2; }
}

__device__ __forceinline__ float lrelu(float x) { return x > 0.f ? x : 0.2f * x; }

// ---------------- layer 1 aggregation + bias + LN(256) + ReLU --------------
__global__ __launch_bounds__(64) void k_agg1(const float* __restrict__ b1,
                                             const float* __restrict__ lng,
                                             const float* __restrict__ lnb) {
    int d = blockIdx.x;
    int t = threadIdx.x;
    int hd = t >> 4; // 4 heads x 16 threads
    __shared__ int s_src[64];
    __shared__ float s_w[64 * 4];
    __shared__ float rs[2], rq[2];
    __shared__ float s_ad[4];
    if (t < 4) s_ad[t] = g_aldst1[d * 4 + t];
    int beg = g_rowptr[d], end = g_rowptr[d + 1];
    float4 acc = make_float4(0.f, 0.f, 0.f, 0.f);
    float wsum = 0.f;
    for (int base = beg; base < end; base += 64) {
        int nE = min(64, end - base);
        if (t < nE) s_src[t] = g_esrc[base + t];
        __syncthreads();
        for (int idx = t; idx < nE * 4; idx += 64) {
            int e = idx >> 2, h2 = idx & 3;
            float v = g_alsrc1[s_src[e] * 4 + h2] + s_ad[h2];
            s_w[idx] = __expf(lrelu(v));
        }
        __syncthreads();
        for (int j = 0; j < nE; j++) {
            int s = s_src[j];
            float w = s_w[j * 4 + hd];
            uint2 u = *reinterpret_cast<const uint2*>(g_h1 + (size_t)s * 256 + t * 4);
            float2 f0 = __half22float2(*reinterpret_cast<__half2*>(&u.x));
            float2 f1 = __half22float2(*reinterpret_cast<__half2*>(&u.y));
            acc.x += w * f0.x; acc.y += w * f0.y;
            acc.z += w * f1.x; acc.w += w * f1.y;
            wsum += w;
        }
        __syncthreads();
    }
    float inv = 1.f / wsum;
    float4 bv = *reinterpret_cast<const float4*>(b1 + t * 4);
    float4 o;
    o.x = acc.x * inv + bv.x; o.y = acc.y * inv + bv.y;
    o.z = acc.z * inv + bv.z; o.w = acc.w * inv + bv.w;
    float s = o.x + o.y + o.z + o.w;
    float q = o.x * o.x + o.y * o.y + o.z * o.z + o.w * o.w;
#pragma unroll
    for (int off = 16; off; off >>= 1) {
        s += __shfl_xor_sync(0xffffffffu, s, off);
        q += __shfl_xor_sync(0xffffffffu, q, off);
    }
    if ((t & 31) == 0) { rs[t >> 5] = s; rq[t >> 5] = q; }
    __syncthreads();
    float S = rs[0] + rs[1], Q = rq[0] + rq[1];
    float mu = S * (1.f / 256.f);
    float var = Q * (1.f / 256.f) - mu * mu;
    float rstd = rsqrtf(var + 1e-5f);
    float4 gv = *reinterpret_cast<const float4*>(lng + t * 4);
    float4 nbv = *reinterpret_cast<const float4*>(lnb + t * 4);
    o.x = fmaxf((o.x - mu) * rstd * gv.x + nbv.x, 0.f);
    o.y = fmaxf((o.y - mu) * rstd * gv.y + nbv.y, 0.f);
    o.z = fmaxf((o.z - mu) * rstd * gv.z + nbv.z, 0.f);
    o.w = fmaxf((o.w - mu) * rstd * gv.w + nbv.w, 0.f);
    *reinterpret_cast<float4*>(g_h1n + (size_t)d * 256 + t * 4) = o;
}

// ---------------- layer 2 aggregation + LN(64) + ReLU + MLP head -----------
__global__ __launch_bounds__(64) void k_agg2(const float* __restrict__ b2,
                                             const float* __restrict__ lng,
                                             const float* __restrict__ lnb,
                                             const float* __restrict__ f1W,
                                             const float* __restrict__ f1b,
                                             const float* __restrict__ f2W,
                                             const float* __restrict__ f2b,
                                             float* __restrict__ out) {
    int d = blockIdx.x;
    int t = threadIdx.x;
    __shared__ int s_src[64];
    __shared__ float s_w[64];
    __shared__ __align__(16) float hn[64];
    int beg = g_rowptr[d], end = g_rowptr[d + 1];
    float ad2 = g_aldst2[d];
    float4 acc = make_float4(0.f, 0.f, 0.f, 0.f);
    float wsum = 0.f;
    for (int base = beg; base < end; base += 64) {
        int nE = min(64, end - base);
        if (t < nE) {
            int s = g_esrc[base + t];
            s_src[t] = s;
            s_w[t] = __expf(lrelu(g_alsrc2[s] + ad2));
        }
        __syncthreads();
        if (t < 16) {
            for (int j = 0; j < nE; j++) {
                int s = s_src[j];
                float w = s_w[j];
                uint2 u = *reinterpret_cast<const uint2*>(g_h2 + (size_t)s * 64 + t * 4);
                float2 f0 = __half22float2(*reinterpret_cast<__half2*>(&u.x));
                float2 f1 = __half22float2(*reinterpret_cast<__half2*>(&u.y));
                acc.x += w * f0.x; acc.y += w * f0.y;
                acc.z += w * f1.x; acc.w += w * f1.y;
                wsum += w;
            }
        }
        __syncthreads();
    }
    if (t < 16) {
        float inv = 1.f / wsum;
        float4 bv = *reinterpret_cast<const float4*>(b2 + t * 4);
        float4 o;
        o.x = acc.x * inv + bv.x; o.y = acc.y * inv + bv.y;
        o.z = acc.z * inv + bv.z; o.w = acc.w * inv + bv.w;
        float s = o.x + o.y + o.z + o.w;
        float q = o.x * o.x + o.y * o.y + o.z * o.z + o.w * o.w;
#pragma unroll
        for (int off = 8; off; off >>= 1) {
            s += __shfl_xor_sync(0x0000ffffu, s, off);
            q += __shfl_xor_sync(0x0000ffffu, q, off);
        }
        float mu = s * (1.f / 64.f);
        float var = q * (1.f / 64.f) - mu * mu;
        float rstd = rsqrtf(var + 1e-5f);
        float4 gv = *reinterpret_cast<const float4*>(lng + t * 4);
        float4 nbv = *reinterpret_cast<const float4*>(lnb + t * 4);
        float4 y;
        y.x = fmaxf((o.x - mu) * rstd * gv.x + nbv.x, 0.f);
        y.y = fmaxf((o.y - mu) * rstd * gv.y + nbv.y, 0.f);
        y.z = fmaxf((o.z - mu) * rstd * gv.z + nbv.z, 0.f);
        y.w = fmaxf((o.w - mu) * rstd * gv.w + nbv.w, 0.f);
        *reinterpret_cast<float4*>(&hn[t * 4]) = y;
    }
    __syncthreads();
    if (t < 32) {
        float r = f1b[t];
#pragma unroll
        for (int k = 0; k < 64; k++) r += hn[k] * f1W[k * 32 + t];
        float v = fmaxf(r, 0.f) * f2W[t];
#pragma unroll
        for (int off = 16; off; off >>= 1) v += __shfl_down_sync(0xffffffffu, v, off);
        if (t == 0) out[d] = v + f2b[0];
    }
}

// ---------------- host launcher --------------------------------------------
extern "C" void kernel_launch(void* const* d_in, const int* in_sizes, int n_in,
                              void* d_out, int out_size) {
    const float* x       = (const float*)d_in[0];
    const void*  ei      = d_in[1];                 // int32 OR int64, auto-detected
    const float* W1      = (const float*)d_in[2];
    const float* as1     = (const float*)d_in[3];
    const float* ad1     = (const float*)d_in[4];
    const float* b1      = (const float*)d_in[5];
    const float* g1      = (const float*)d_in[6];
    const float* bb1     = (const float*)d_in[7];
    const float* W2      = (const float*)d_in[8];
    const float* as2     = (const float*)d_in[9];
    const float* ad2     = (const float*)d_in[10];
    const float* b2      = (const float*)d_in[11];
    const float* g2      = (const float*)d_in[12];
    const float* bb2     = (const float*)d_in[13];
    const float* f1W     = (const float*)d_in[14];
    const float* f1b     = (const float*)d_in[15];
    const float* f2W     = (const float*)d_in[16];
    const float* f2b     = (const float*)d_in[17];
    float* out = (float*)d_out;

    int N = in_sizes[0] / 128;
    int E = in_sizes[1] / 2;
    int ET = E + N;
    int nblk = (N + SCAN_TILE - 1) / SCAN_TILE;

    __half *h1p, *h2p;
    float *h1np, *als1p, *ald1p, *als2p, *ald2p;
    cudaGetSymbolAddress((void**)&h1p,   g_h1);
    cudaGetSymbolAddress((void**)&h1np,  g_h1n);
    cudaGetSymbolAddress((void**)&h2p,   g_h2);
    cudaGetSymbolAddress((void**)&als1p, g_alsrc1);
    cudaGetSymbolAddress((void**)&ald1p, g_aldst1);
    cudaGetSymbolAddress((void**)&als2p, g_alsrc2);
    cudaGetSymbolAddress((void**)&ald2p, g_aldst2);

    // smem for the larger GEMM (K=256): 2 * 64 * 264 halves = 67,584 B
    static int smem_attr_set = 0;
    if (!smem_attr_set) {
        cudaFuncSetAttribute(k_gemm_mma<__half>,
                             cudaFuncAttributeMaxDynamicSharedMemorySize, 69632);
        smem_attr_set = 1;
    }
    int smem1 = 2 * 64 * (128 + 8) * (int)sizeof(__half); // 34,816
    int smem2 = 2 * 64 * (256 + 8) * (int)sizeof(__half); // 67,584

    // CSR build (dst-sorted)
    k_detect <<<1, 1>>>(ei);
    k_zero   <<<(N + 255) / 256, 256>>>(N);
    k_count  <<<(ET + 255) / 256, 256>>>(ei, E, N);
    k_scan1  <<<nblk, 256>>>(N);
    k_scan2  <<<1, 64>>>(nblk, N);
    k_scan3  <<<nblk, 256>>>(N);
    k_scatter<<<(ET + 255) / 256, 256>>>(ei, E, N);

    // Layer 1
    k_gemm_mma<__half><<<dim3((N + 63) / 64, 4), 128, smem1>>>(x, W1, h1p, N, 256, 128);
    k_al  <<<(N * 4 + 7) / 8, 256>>>(h1p, as1, ad1, als1p, ald1p, N, 4);
    k_agg1<<<N, 64>>>(b1, g1, bb1);

    // Layer 2
    k_gemm_mma<__half><<<dim3((N + 63) / 64, 1), 128, smem2>>>(h1np, W2, h2p, N, 64, 256);
    k_al  <<<(N + 7) / 8, 256>>>(h2p, as2, ad2, als2p, ald2p, N, 1);
    k_agg2<<<N, 64>>>(b2, g2, bb2, f1W, f1b, f2W, f2b, out);

    (void)n_in; (void)out_size;
}

// round 14
// speedup vs baseline: 1.9696x; 1.1931x over previous
#include <cuda_runtime.h>
#include <cuda_fp16.h>
#include <math.h>

// ---------------- compile-time capacity (N=50000, E=800000 per dataset) ----
#define N_MAX 50048
#define ET_MAX 852000
#define SCAN_TILE 1024
#define NBLK_MAX 64

// ---------------- device scratch (allowed: __device__ globals) -------------
__device__ __align__(16) __half g_h1 [(size_t)N_MAX * 256]; // x @ W1 (fp16 gather table)
__device__ __align__(16) float g_h1n [(size_t)N_MAX * 256]; // after agg1+LN+ReLU (fp32)
__device__ __align__(16) __half g_h2 [(size_t)N_MAX * 64];  // h1n @ W2 (fp16 gather table)
__device__ __align__(16) float g_alsrc1[(size_t)N_MAX * 4];
__device__ __align__(16) float g_aldst1[(size_t)N_MAX * 4];
__device__ __align__(16) float g_alsrc2[N_MAX];
__device__ __align__(16) float g_aldst2[N_MAX];
__device__ __align__(16) int g_deg[N_MAX + 4];
__device__ __align__(16) int g_rowptr[N_MAX + 4];
__device__ __align__(16) int g_wcur[N_MAX];
__device__ int g_esrc[ET_MAX];
__device__ int g_blksum[NBLK_MAX];
__device__ int g_idx_is64;

// ---------------- init: zero degrees + edge-index dtype detection ----------
__global__ void k_init(const void* __restrict__ ei, int N) {
    int t = blockIdx.x * blockDim.x + threadIdx.x;
    if (t < N) g_deg[t] = 0;
    if (t == 0) {
        // int64 little-endian indices < 2^31 have all-zero high words
        const unsigned int* p = (const unsigned int*)ei;
        int is64 = 1;
        for (int i = 0; i < 64; i++) {
            if (p[2 * i + 1] != 0u) { is64 = 0; break; }
        }
        g_idx_is64 = is64;
    }
}

__device__ __forceinline__ int load_idx(const void* __restrict__ ei,
                                        long long pos, int is64, int N) {
    int v = is64 ? (int)((const long long*)ei)[pos]
                 : ((const int*)ei)[pos];
    v = v < 0 ? 0 : (v >= N ? N - 1 : v);
    return v;
}

__global__ void k_count(const void* __restrict__ ei, int E, int N) {
    int t = blockIdx.x * blockDim.x + threadIdx.x;
    int ET = E + N;
    if (t >= ET) return;
    int is64 = g_idx_is64;
    int dst = (t < E) ? load_idx(ei, (long long)E + t, is64, N) : (t - E);
    atomicAdd(&g_deg[dst], 1);
}

// ---------------- 2-phase multi-block exclusive scan of g_deg --------------
__device__ __forceinline__ int4 load_deg4(int base, int N) {
    int4 v = make_int4(0, 0, 0, 0);
    if (base + 3 < N) {
        v = *reinterpret_cast<const int4*>(g_deg + base);
    } else {
        if (base + 0 < N) v.x = g_deg[base + 0];
        if (base + 1 < N) v.y = g_deg[base + 1];
        if (base + 2 < N) v.z = g_deg[base + 2];
        if (base + 3 < N) v.w = g_deg[base + 3];
    }
    return v;
}

__global__ __launch_bounds__(256) void k_scan1(int N) {
    int tid = threadIdx.x;
    int lane = tid & 31, wid = tid >> 5;
    int base = blockIdx.x * SCAN_TILE + tid * 4;
    int4 v = load_deg4(base, N);
    int s = v.x + v.y + v.z + v.w;
#pragma unroll
    for (int off = 16; off; off >>= 1) s += __shfl_xor_sync(0xffffffffu, s, off);
    __shared__ int ws[8];
    if (lane == 0) ws[wid] = s;
    __syncthreads();
    if (tid == 0) {
        int tot = 0;
#pragma unroll
        for (int i = 0; i < 8; i++) tot += ws[i];
        g_blksum[blockIdx.x] = tot;
    }
}

// phase 2+3 merged: every block redundantly scans blksums in smem
__global__ __launch_bounds__(256) void k_scan3(int N, int nblk) {
    int tid = threadIdx.x;
    int lane = tid & 31, wid = tid >> 5;
    __shared__ int bs[NBLK_MAX];
    if (tid < nblk) bs[tid] = g_blksum[tid];
    __syncthreads();
    if (tid == 0) {
        int run = 0;
        for (int i = 0; i < nblk; i++) { int v = bs[i]; bs[i] = run; run += v; }
        if (blockIdx.x == 0) g_rowptr[N] = run;
    }
    __syncthreads();
    int blkoff = bs[blockIdx.x];

    int base = blockIdx.x * SCAN_TILE + tid * 4;
    int4 v = load_deg4(base, N);
    int t1 = v.x, t2 = t1 + v.y, t3 = t2 + v.z, t4 = t3 + v.w;
    int s = t4;
#pragma unroll
    for (int off = 1; off < 32; off <<= 1) {
        int u = __shfl_up_sync(0xffffffffu, s, off);
        if (lane >= off) s += u;
    }
    __shared__ int ws[8];
    if (lane == 31) ws[wid] = s;
    __syncthreads();
    if (wid == 0 && lane < 8) {
        int w = ws[lane];
#pragma unroll
        for (int off = 1; off < 8; off <<= 1) {
            int u = __shfl_up_sync(0x000000ffu, w, off);
            if (lane >= off) w += u;
        }
        ws[lane] = w;
    }
    __syncthreads();
    int excl = s - t4 + (wid ? ws[wid - 1] : 0);
    int off0 = blkoff + excl;
    if (base + 0 < N) { g_rowptr[base + 0] = off0;      g_wcur[base + 0] = off0; }
    if (base + 1 < N) { g_rowptr[base + 1] = off0 + t1; g_wcur[base + 1] = off0 + t1; }
    if (base + 2 < N) { g_rowptr[base + 2] = off0 + t2; g_wcur[base + 2] = off0 + t2; }
    if (base + 3 < N) { g_rowptr[base + 3] = off0 + t3; g_wcur[base + 3] = off0 + t3; }
}

__global__ void k_scatter(const void* __restrict__ ei, int E, int N) {
    int t = blockIdx.x * blockDim.x + threadIdx.x;
    int ET = E + N;
    if (t >= ET) return;
    int is64 = g_idx_is64;
    int src, dst;
    if (t < E) {
        src = load_idx(ei, t, is64, N);
        dst = load_idx(ei, (long long)E + t, is64, N);
    } else {
        src = t - E; dst = t - E;
    }
    int pos = atomicAdd(&g_wcur[dst], 1);
    g_esrc[pos] = src;
}

// ---------------- output stores ---------------------------------------------
__device__ __forceinline__ void store2(float* p, float a, float b) {
    p[0] = a; p[1] = b;
}
__device__ __forceinline__ void store2(__half* p, float a, float b) {
    *reinterpret_cast<__half2*>(p) = __floats2half2_rn(a, b);
}

// ---------------- tensor-core GEMM + fused attention logits -----------------
// C[M,Nt] = A[M,K] @ B[K,Nt]; blockIdx.y is a 64-col slice == one head.
// Epilogue also computes alsrc[row*H+hd] = sum_col C*asv, aldst likewise.
template <typename OT>
__global__ __launch_bounds__(128) void k_gemm_mma(const float* __restrict__ A,
                                                  const float* __restrict__ B,
                                                  OT* __restrict__ C,
                                                  const float* __restrict__ asv,
                                                  const float* __restrict__ adv,
                                                  float* __restrict__ alsrc,
                                                  float* __restrict__ aldst,
                                                  int M, int Nt, int K, int H) {
    extern __shared__ __half smh[];
    int rs = K + 8;                 // halves per row
    __half* As = smh;               // 64 x rs
    __half* Bs = smh + 64 * rs;     // 64 x rs
    int tid = threadIdx.x;
    int warp = tid >> 5, lane = tid & 31;
    int m0 = blockIdx.x * 64, n0 = blockIdx.y * 64;
    int hd = blockIdx.y;

    // ---- load A tile (convert fp32->fp16) ----
    int kq4 = K >> 2;
    for (int id = tid; id < 64 * kq4; id += 128) {
        int row = id / kq4, kq = id - row * kq4;
        float4 v = make_float4(0.f, 0.f, 0.f, 0.f);
        int gr = m0 + row;
        if (gr < M) v = *reinterpret_cast<const float4*>(A + (size_t)gr * K + kq * 4);
        __half* dst = As + row * rs + kq * 4;
        *reinterpret_cast<__half2*>(dst) = __floats2half2_rn(v.x, v.y);
        *reinterpret_cast<__half2*>(dst + 2) = __floats2half2_rn(v.z, v.w);
    }
    // ---- load B tile transposed: Bs[n][k] = B[k][n0+n] ----
    for (int id = tid; id < K * 16; id += 128) {
        int k = id >> 4, nq = id & 15;
        float4 v = *reinterpret_cast<const float4*>(B + (size_t)k * Nt + n0 + nq * 4);
        Bs[(nq * 4 + 0) * rs + k] = __float2half_rn(v.x);
        Bs[(nq * 4 + 1) * rs + k] = __float2half_rn(v.y);
        Bs[(nq * 4 + 2) * rs + k] = __float2half_rn(v.z);
        Bs[(nq * 4 + 3) * rs + k] = __float2half_rn(v.w);
    }
    __syncthreads();

    int g = lane >> 2, tig = lane & 3;
    int rs32 = rs >> 1;
    const unsigned int* As32 = reinterpret_cast<const unsigned int*>(As);
    const unsigned int* Bs32 = reinterpret_cast<const unsigned int*>(Bs);
    int mrow = warp * 16 + g;

    float c[8][4];
#pragma unroll
    for (int i = 0; i < 8; i++)
#pragma unroll
        for (int j = 0; j < 4; j++) c[i][j] = 0.f;

    int nks = K >> 4;
    for (int ks = 0; ks < nks; ks++) {
        unsigned int a0 = As32[(size_t)mrow * rs32 + ks * 8 + tig];
        unsigned int a1 = As32[(size_t)(mrow + 8) * rs32 + ks * 8 + tig];
        unsigned int a2 = As32[(size_t)mrow * rs32 + ks * 8 + 4 + tig];
        unsigned int a3 = As32[(size_t)(mrow + 8) * rs32 + ks * 8 + 4 + tig];
#pragma unroll
        for (int nt = 0; nt < 8; nt++) {
            int n = nt * 8 + g;
            unsigned int b0 = Bs32[(size_t)n * rs32 + ks * 8 + tig];
            unsigned int b1 = Bs32[(size_t)n * rs32 + ks * 8 + 4 + tig];
            asm volatile(
                "mma.sync.aligned.m16n8k16.row.col.f32.f16.f16.f32 "
                "{%0,%1,%2,%3},{%4,%5,%6,%7},{%8,%9},{%0,%1,%2,%3};"
                : "+f"(c[nt][0]), "+f"(c[nt][1]), "+f"(c[nt][2]), "+f"(c[nt][3])
                : "r"(a0), "r"(a1), "r"(a2), "r"(a3), "r"(b0), "r"(b1));
        }
    }

    // ---- epilogue: store C + fused attention logits ----
    int gr0 = m0 + warp * 16 + g;
    int gr1 = gr0 + 8;
    float s1a = 0.f, s2a = 0.f, s1b = 0.f, s2b = 0.f;
#pragma unroll
    for (int nt = 0; nt < 8; nt++) {
        int lc = nt * 8 + tig * 2;
        int gc = n0 + lc;
        if (gr0 < M) store2(C + (size_t)gr0 * Nt + gc, c[nt][0], c[nt][1]);
        if (gr1 < M) store2(C + (size_t)gr1 * Nt + gc, c[nt][2], c[nt][3]);
        float a0 = asv[hd * 64 + lc], a1 = asv[hd * 64 + lc + 1];
        float d0 = adv[hd * 64 + lc], d1 = adv[hd * 64 + lc + 1];
        s1a += c[nt][0] * a0 + c[nt][1] * a1;
        s2a += c[nt][0] * d0 + c[nt][1] * d1;
        s1b += c[nt][2] * a0 + c[nt][3] * a1;
        s2b += c[nt][2] * d0 + c[nt][3] * d1;
    }
#pragma unroll
    for (int off = 1; off < 4; off <<= 1) {
        s1a += __shfl_xor_sync(0xffffffffu, s1a, off);
        s2a += __shfl_xor_sync(0xffffffffu, s2a, off);
        s1b += __shfl_xor_sync(0xffffffffu, s1b, off);
        s2b += __shfl_xor_sync(0xffffffffu, s2b, off);
    }
    if (tig == 0) {
        if (gr0 < M) { alsrc[(size_t)gr0 * H + hd] = s1a; aldst[(size_t)gr0 * H + hd] = s2a; }
        if (gr1 < M) { alsrc[(size_t)gr1 * H + hd] = s1b; aldst[(size_t)gr1 * H + hd] = s2b; }
    }
}

__device__ __forceinline__ float lrelu(float x) { return x > 0.f ? x : 0.2f * x; }

// ---------------- layer 1 aggregation + bias + LN(256) + ReLU --------------
__global__ __launch_bounds__(64) void k_agg1(const float* __restrict__ b1,
                                             const float* __restrict__ lng,
                                             const float* __restrict__ lnb) {
    int d = blockIdx.x;
    int t = threadIdx.x;
    int hd = t >> 4; // 4 heads x 16 threads
    __shared__ int s_src[64];
    __shared__ float s_w[64 * 4];
    __shared__ float rs[2], rq[2];
    __shared__ float s_ad[4];
    if (t < 4) s_ad[t] = g_aldst1[d * 4 + t];
    int beg = g_rowptr[d], end = g_rowptr[d + 1];
    float4 acc = make_float4(0.f, 0.f, 0.f, 0.f);
    float wsum = 0.f;
    for (int base = beg; base < end; base += 64) {
        int nE = min(64, end - base);
        if (t < nE) s_src[t] = g_esrc[base + t];
        __syncthreads();
        for (int idx = t; idx < nE * 4; idx += 64) {
            int e = idx >> 2, h2 = idx & 3;
            float v = g_alsrc1[s_src[e] * 4 + h2] + s_ad[h2];
            s_w[idx] = __expf(lrelu(v));
        }
        __syncthreads();
        int j = 0;
        for (; j + 2 <= nE; j += 2) {
            int s0 = s_src[j], s1v = s_src[j + 1];
            float w0 = s_w[j * 4 + hd], w1 = s_w[(j + 1) * 4 + hd];
            uint2 u0 = *reinterpret_cast<const uint2*>(g_h1 + (size_t)s0 * 256 + t * 4);
            uint2 u1 = *reinterpret_cast<const uint2*>(g_h1 + (size_t)s1v * 256 + t * 4);
            float2 a0 = __half22float2(*reinterpret_cast<__half2*>(&u0.x));
            float2 a1 = __half22float2(*reinterpret_cast<__half2*>(&u0.y));
            float2 b0 = __half22float2(*reinterpret_cast<__half2*>(&u1.x));
            float2 b1 = __half22float2(*reinterpret_cast<__half2*>(&u1.y));
            acc.x += w0 * a0.x + w1 * b0.x;
            acc.y += w0 * a0.y + w1 * b0.y;
            acc.z += w0 * a1.x + w1 * b1.x;
            acc.w += w0 * a1.y + w1 * b1.y;
            wsum += w0 + w1;
        }
        if (j < nE) {
            int s0 = s_src[j];
            float w0 = s_w[j * 4 + hd];
            uint2 u0 = *reinterpret_cast<const uint2*>(g_h1 + (size_t)s0 * 256 + t * 4);
            float2 a0 = __half22float2(*reinterpret_cast<__half2*>(&u0.x));
            float2 a1 = __half22float2(*reinterpret_cast<__half2*>(&u0.y));
            acc.x += w0 * a0.x; acc.y += w0 * a0.y;
            acc.z += w0 * a1.x; acc.w += w0 * a1.y;
            wsum += w0;
        }
        __syncthreads();
    }
    float inv = 1.f / wsum;
    float4 bv = *reinterpret_cast<const float4*>(b1 + t * 4);
    float4 o;
    o.x = acc.x * inv + bv.x; o.y = acc.y * inv + bv.y;
    o.z = acc.z * inv + bv.z; o.w = acc.w * inv + bv.w;
    float s = o.x + o.y + o.z + o.w;
    float q = o.x * o.x + o.y * o.y + o.z * o.z + o.w * o.w;
#pragma unroll
    for (int off = 16; off; off >>= 1) {
        s += __shfl_xor_sync(0xffffffffu, s, off);
        q += __shfl_xor_sync(0xffffffffu, q, off);
    }
    if ((t & 31) == 0) { rs[t >> 5] = s; rq[t >> 5] = q; }
    __syncthreads();
    float S = rs[0] + rs[1], Q = rq[0] + rq[1];
    float mu = S * (1.f / 256.f);
    float var = Q * (1.f / 256.f) - mu * mu;
    float rstd = rsqrtf(var + 1e-5f);
    float4 gv = *reinterpret_cast<const float4*>(lng + t * 4);
    float4 nbv = *reinterpret_cast<const float4*>(lnb + t * 4);
    o.x = fmaxf((o.x - mu) * rstd * gv.x + nbv.x, 0.f);
    o.y = fmaxf((o.y - mu) * rstd * gv.y + nbv.y, 0.f);
    o.z = fmaxf((o.z - mu) * rstd * gv.z + nbv.z, 0.f);
    o.w = fmaxf((o.w - mu) * rstd * gv.w + nbv.w, 0.f);
    *reinterpret_cast<float4*>(g_h1n + (size_t)d * 256 + t * 4) = o;
}

// ---------------- layer 2: 4 dst nodes per 64-thread block ------------------
// group of 16 threads per node; no smem edge staging (broadcast loads).
__global__ __launch_bounds__(64) void k_agg2(const float* __restrict__ b2,
                                             const float* __restrict__ lng,
                                             const float* __restrict__ lnb,
                                             const float* __restrict__ f1W,
                                             const float* __restrict__ f1b,
                                             const float* __restrict__ f2W,
                                             const float* __restrict__ f2b,
                                             float* __restrict__ out, int N) {
    int t = threadIdx.x;
    int grp = t >> 4, tg = t & 15;
    int d = blockIdx.x * 4 + grp;
    __shared__ __align__(16) float hn[4][64];
    bool act = d < N;
    int beg = 0, end = 0;
    float ad2v = 0.f;
    if (act) { beg = g_rowptr[d]; end = g_rowptr[d + 1]; ad2v = g_aldst2[d]; }
    float4 acc = make_float4(0.f, 0.f, 0.f, 0.f);
    float wsum = 0.f;
    for (int j = beg; j < end; j++) {
        int s = g_esrc[j];
        float w = __expf(lrelu(g_alsrc2[s] + ad2v));
        uint2 u = *reinterpret_cast<const uint2*>(g_h2 + (size_t)s * 64 + tg * 4);
        float2 f0 = __half22float2(*reinterpret_cast<__half2*>(&u.x));
        float2 f1 = __half22float2(*reinterpret_cast<__half2*>(&u.y));
        acc.x += w * f0.x; acc.y += w * f0.y;
        acc.z += w * f1.x; acc.w += w * f1.y;
        wsum += w;
    }
    if (act) {
        float inv = 1.f / wsum;
        float4 bv = *reinterpret_cast<const float4*>(b2 + tg * 4);
        float4 o;
        o.x = acc.x * inv + bv.x; o.y = acc.y * inv + bv.y;
        o.z = acc.z * inv + bv.z; o.w = acc.w * inv + bv.w;
        float s = o.x + o.y + o.z + o.w;
        float q = o.x * o.x + o.y * o.y + o.z * o.z + o.w * o.w;
#pragma unroll
        for (int off = 8; off; off >>= 1) {
            s += __shfl_xor_sync(0xffffffffu, s, off, 16);
            q += __shfl_xor_sync(0xffffffffu, q, off, 16);
        }
        float mu = s * (1.f / 64.f);
        float var = q * (1.f / 64.f) - mu * mu;
        float rstd = rsqrtf(var + 1e-5f);
        float4 gv = *reinterpret_cast<const float4*>(lng + tg * 4);
        float4 nbv = *reinterpret_cast<const float4*>(lnb + tg * 4);
        float4 y;
        y.x = fmaxf((o.x - mu) * rstd * gv.x + nbv.x, 0.f);
        y.y = fmaxf((o.y - mu) * rstd * gv.y + nbv.y, 0.f);
        y.z = fmaxf((o.z - mu) * rstd * gv.z + nbv.z, 0.f);
        y.w = fmaxf((o.w - mu) * rstd * gv.w + nbv.w, 0.f);
        *reinterpret_cast<float4*>(&hn[grp][tg * 4]) = y;
    }
    __syncwarp();
    // MLP head: thread tg computes hidden units tg and tg+16 of its group's node
    if (act) {
        float r0 = f1b[tg], r1 = f1b[tg + 16];
#pragma unroll
        for (int k = 0; k < 64; k++) {
            float h = hn[grp][k];
            r0 += h * f1W[k * 32 + tg];
            r1 += h * f1W[k * 32 + tg + 16];
        }
        float v = fmaxf(r0, 0.f) * f2W[tg] + fmaxf(r1, 0.f) * f2W[tg + 16];
#pragma unroll
        for (int off = 8; off; off >>= 1) v += __shfl_xor_sync(0xffffffffu, v, off, 16);
        if (tg == 0) out[d] = v + f2b[0];
    }
}

// ---------------- host launcher --------------------------------------------
extern "C" void kernel_launch(void* const* d_in, const int* in_sizes, int n_in,
                              void* d_out, int out_size) {
    const float* x       = (const float*)d_in[0];
    const void*  ei      = d_in[1];                 // int32 OR int64, auto-detected
    const float* W1      = (const float*)d_in[2];
    const float* as1     = (const float*)d_in[3];
    const float* ad1     = (const float*)d_in[4];
    const float* b1      = (const float*)d_in[5];
    const float* g1      = (const float*)d_in[6];
    const float* bb1     = (const float*)d_in[7];
    const float* W2      = (const float*)d_in[8];
    const float* as2     = (const float*)d_in[9];
    const float* ad2     = (const float*)d_in[10];
    const float* b2      = (const float*)d_in[11];
    const float* g2      = (const float*)d_in[12];
    const float* bb2     = (const float*)d_in[13];
    const float* f1W     = (const float*)d_in[14];
    const float* f1b     = (const float*)d_in[15];
    const float* f2W     = (const float*)d_in[16];
    const float* f2b     = (const float*)d_in[17];
    float* out = (float*)d_out;

    int N = in_sizes[0] / 128;
    int E = in_sizes[1] / 2;
    int ET = E + N;
    int nblk = (N + SCAN_TILE - 1) / SCAN_TILE;

    __half *h1p, *h2p;
    float *h1np, *als1p, *ald1p, *als2p, *ald2p;
    cudaGetSymbolAddress((void**)&h1p,   g_h1);
    cudaGetSymbolAddress((void**)&h1np,  g_h1n);
    cudaGetSymbolAddress((void**)&h2p,   g_h2);
    cudaGetSymbolAddress((void**)&als1p, g_alsrc1);
    cudaGetSymbolAddress((void**)&ald1p, g_aldst1);
    cudaGetSymbolAddress((void**)&als2p, g_alsrc2);
    cudaGetSymbolAddress((void**)&ald2p, g_aldst2);

    static int smem_attr_set = 0;
    if (!smem_attr_set) {
        cudaFuncSetAttribute(k_gemm_mma<__half>,
                             cudaFuncAttributeMaxDynamicSharedMemorySize, 69632);
        smem_attr_set = 1;
    }
    int smem1 = 2 * 64 * (128 + 8) * (int)sizeof(__half); // 34,816
    int smem2 = 2 * 64 * (256 + 8) * (int)sizeof(__half); // 67,584

    // CSR build (dst-sorted)
    k_init   <<<(N + 255) / 256, 256>>>(ei, N);
    k_count  <<<(ET + 255) / 256, 256>>>(ei, E, N);
    k_scan1  <<<nblk, 256>>>(N);
    k_scan3  <<<nblk, 256>>>(N, nblk);
    k_scatter<<<(ET + 255) / 256, 256>>>(ei, E, N);

    // Layer 1 (GEMM + fused attention logits)
    k_gemm_mma<__half><<<dim3((N + 63) / 64, 4), 128, smem1>>>(
        x, W1, h1p, as1, ad1, als1p, ald1p, N, 256, 128, 4);
    k_agg1<<<N, 64>>>(b1, g1, bb1);

    // Layer 2 (GEMM + fused attention logits)
    k_gemm_mma<__half><<<dim3((N + 63) / 64, 1), 128, smem2>>>(
        h1np, W2, h2p, as2, ad2, als2p, ald2p, N, 64, 256, 1);
    k_agg2<<<(N + 3) / 4, 64>>>(b2, g2, bb2, f1W, f1b, f2W, f2b, out, N);

    (void)n_in; (void)out_size;
}

// round 17
// speedup vs baseline: 2.0635x; 1.0477x over previous
#include <cuda_runtime.h>
#include <cuda_fp16.h>
#include <math.h>

// ---------------- compile-time capacity (N=50000, E=800000 per dataset) ----
#define N_MAX 50048
#define ET_MAX 852000
#define SCAN_TILE 1024
#define NBLK_MAX 64

// ---------------- device scratch (allowed: __device__ globals) -------------
__device__ __align__(16) __half g_h1 [(size_t)N_MAX * 256]; // x @ W1 (fp16 gather table)
__device__ __align__(16) float g_h1n [(size_t)N_MAX * 256]; // after agg1+LN+ReLU (fp32)
__device__ __align__(16) __half g_h2 [(size_t)N_MAX * 64];  // h1n @ W2 (fp16 gather table)
__device__ __align__(16) float g_alsrc1[(size_t)N_MAX * 4];
__device__ __align__(16) float g_aldst1[(size_t)N_MAX * 4];
__device__ __align__(16) float g_alsrc2[N_MAX];
__device__ __align__(16) float g_aldst2[N_MAX];
__device__ __align__(16) int g_deg[N_MAX + 4];
__device__ __align__(16) int g_rowptr[N_MAX + 4];
__device__ __align__(16) int g_wcur[N_MAX];
__device__ int g_esrc[ET_MAX];
__device__ int g_blksum[NBLK_MAX];
__device__ int g_idx_is64;

// ---------------- init: zero degrees + edge-index dtype detection ----------
__global__ void k_init(const void* __restrict__ ei, int N) {
    int t = blockIdx.x * blockDim.x + threadIdx.x;
    if (t < N) g_deg[t] = 0;
    if (t == 0) {
        const unsigned int* p = (const unsigned int*)ei;
        int is64 = 1;
        for (int i = 0; i < 64; i++) {
            if (p[2 * i + 1] != 0u) { is64 = 0; break; }
        }
        g_idx_is64 = is64;
    }
}

__device__ __forceinline__ int load_idx(const void* __restrict__ ei,
                                        long long pos, int is64, int N) {
    int v = is64 ? (int)((const long long*)ei)[pos]
                 : ((const int*)ei)[pos];
    v = v < 0 ? 0 : (v >= N ? N - 1 : v);
    return v;
}

__global__ void k_count(const void* __restrict__ ei, int E, int N) {
    int t = blockIdx.x * blockDim.x + threadIdx.x;
    int ET = E + N;
    if (t >= ET) return;
    int is64 = g_idx_is64;
    int dst = (t < E) ? load_idx(ei, (long long)E + t, is64, N) : (t - E);
    atomicAdd(&g_deg[dst], 1);
}

// ---------------- 2-phase multi-block exclusive scan of g_deg --------------
__device__ __forceinline__ int4 load_deg4(int base, int N) {
    int4 v = make_int4(0, 0, 0, 0);
    if (base + 3 < N) {
        v = *reinterpret_cast<const int4*>(g_deg + base);
    } else {
        if (base + 0 < N) v.x = g_deg[base + 0];
        if (base + 1 < N) v.y = g_deg[base + 1];
        if (base + 2 < N) v.z = g_deg[base + 2];
        if (base + 3 < N) v.w = g_deg[base + 3];
    }
    return v;
}

__global__ __launch_bounds__(256) void k_scan1(int N) {
    int tid = threadIdx.x;
    int lane = tid & 31, wid = tid >> 5;
    int base = blockIdx.x * SCAN_TILE + tid * 4;
    int4 v = load_deg4(base, N);
    int s = v.x + v.y + v.z + v.w;
#pragma unroll
    for (int off = 16; off; off >>= 1) s += __shfl_xor_sync(0xffffffffu, s, off);
    __shared__ int ws[8];
    if (lane == 0) ws[wid] = s;
    __syncthreads();
    if (tid == 0) {
        int tot = 0;
#pragma unroll
        for (int i = 0; i < 8; i++) tot += ws[i];
        g_blksum[blockIdx.x] = tot;
    }
}

// phase 2+3 merged: every block redundantly scans blksums in smem
__global__ __launch_bounds__(256) void k_scan3(int N, int nblk) {
    int tid = threadIdx.x;
    int lane = tid & 31, wid = tid >> 5;
    __shared__ int bs[NBLK_MAX];
    if (tid < nblk) bs[tid] = g_blksum[tid];
    __syncthreads();
    if (tid == 0) {
        int run = 0;
        for (int i = 0; i < nblk; i++) { int v = bs[i]; bs[i] = run; run += v; }
        if (blockIdx.x == 0) g_rowptr[N] = run;
    }
    __syncthreads();
    int blkoff = bs[blockIdx.x];

    int base = blockIdx.x * SCAN_TILE + tid * 4;
    int4 v = load_deg4(base, N);
    int t1 = v.x, t2 = t1 + v.y, t3 = t2 + v.z, t4 = t3 + v.w;
    int s = t4;
#pragma unroll
    for (int off = 1; off < 32; off <<= 1) {
        int u = __shfl_up_sync(0xffffffffu, s, off);
        if (lane >= off) s += u;
    }
    __shared__ int ws[8];
    if (lane == 31) ws[wid] = s;
    __syncthreads();
    if (wid == 0 && lane < 8) {
        int w = ws[lane];
#pragma unroll
        for (int off = 1; off < 8; off <<= 1) {
            int u = __shfl_up_sync(0x000000ffu, w, off);
            if (lane >= off) w += u;
        }
        ws[lane] = w;
    }
    __syncthreads();
    int excl = s - t4 + (wid ? ws[wid - 1] : 0);
    int off0 = blkoff + excl;
    if (base + 0 < N) { g_rowptr[base + 0] = off0;      g_wcur[base + 0] = off0; }
    if (base + 1 < N) { g_rowptr[base + 1] = off0 + t1; g_wcur[base + 1] = off0 + t1; }
    if (base + 2 < N) { g_rowptr[base + 2] = off0 + t2; g_wcur[base + 2] = off0 + t2; }
    if (base + 3 < N) { g_rowptr[base + 3] = off0 + t3; g_wcur[base + 3] = off0 + t3; }
}

__global__ void k_scatter(const void* __restrict__ ei, int E, int N) {
    int t = blockIdx.x * blockDim.x + threadIdx.x;
    int ET = E + N;
    if (t >= ET) return;
    int is64 = g_idx_is64;
    int src, dst;
    if (t < E) {
        src = load_idx(ei, t, is64, N);
        dst = load_idx(ei, (long long)E + t, is64, N);
    } else {
        src = t - E; dst = t - E;
    }
    int pos = atomicAdd(&g_wcur[dst], 1);
    g_esrc[pos] = src;
}

// ---------------- output stores ---------------------------------------------
__device__ __forceinline__ void store2(float* p, float a, float b) {
    p[0] = a; p[1] = b;
}
__device__ __forceinline__ void store2(__half* p, float a, float b) {
    *reinterpret_cast<__half2*>(p) = __floats2half2_rn(a, b);
}

// ---------------- tensor-core GEMM + fused attention logits -----------------
template <typename OT>
__global__ __launch_bounds__(128) void k_gemm_mma(const float* __restrict__ A,
                                                  const float* __restrict__ B,
                                                  OT* __restrict__ C,
                                                  const float* __restrict__ asv,
                                                  const float* __restrict__ adv,
                                                  float* __restrict__ alsrc,
                                                  float* __restrict__ aldst,
                                                  int M, int Nt, int K, int H) {
    extern __shared__ __half smh[];
    int rs = K + 8;                 // halves per row
    __half* As = smh;               // 64 x rs
    __half* Bs = smh + 64 * rs;     // 64 x rs
    int tid = threadIdx.x;
    int warp = tid >> 5, lane = tid & 31;
    int m0 = blockIdx.x * 64, n0 = blockIdx.y * 64;
    int hd = blockIdx.y;

    int kq4 = K >> 2;
    for (int id = tid; id < 64 * kq4; id += 128) {
        int row = id / kq4, kq = id - row * kq4;
        float4 v = make_float4(0.f, 0.f, 0.f, 0.f);
        int gr = m0 + row;
        if (gr < M) v = *reinterpret_cast<const float4*>(A + (size_t)gr * K + kq * 4);
        __half* dst = As + row * rs + kq * 4;
        *reinterpret_cast<__half2*>(dst) = __floats2half2_rn(v.x, v.y);
        *reinterpret_cast<__half2*>(dst + 2) = __floats2half2_rn(v.z, v.w);
    }
    for (int id = tid; id < K * 16; id += 128) {
        int k = id >> 4, nq = id & 15;
        float4 v = *reinterpret_cast<const float4*>(B + (size_t)k * Nt + n0 + nq * 4);
        Bs[(nq * 4 + 0) * rs + k] = __float2half_rn(v.x);
        Bs[(nq * 4 + 1) * rs + k] = __float2half_rn(v.y);
        Bs[(nq * 4 + 2) * rs + k] = __float2half_rn(v.z);
        Bs[(nq * 4 + 3) * rs + k] = __float2half_rn(v.w);
    }
    __syncthreads();

    int g = lane >> 2, tig = lane & 3;
    int rs32 = rs >> 1;
    const unsigned int* As32 = reinterpret_cast<const unsigned int*>(As);
    const unsigned int* Bs32 = reinterpret_cast<const unsigned int*>(Bs);
    int mrow = warp * 16 + g;

    float c[8][4];
#pragma unroll
    for (int i = 0; i < 8; i++)
#pragma unroll
        for (int j = 0; j < 4; j++) c[i][j] = 0.f;

    int nks = K >> 4;
    for (int ks = 0; ks < nks; ks++) {
        unsigned int a0 = As32[(size_t)mrow * rs32 + ks * 8 + tig];
        unsigned int a1 = As32[(size_t)(mrow + 8) * rs32 + ks * 8 + tig];
        unsigned int a2 = As32[(size_t)mrow * rs32 + ks * 8 + 4 + tig];
        unsigned int a3 = As32[(size_t)(mrow + 8) * rs32 + ks * 8 + 4 + tig];
#pragma unroll
        for (int nt = 0; nt < 8; nt++) {
            int n = nt * 8 + g;
            unsigned int b0 = Bs32[(size_t)n * rs32 + ks * 8 + tig];
            unsigned int b1 = Bs32[(size_t)n * rs32 + ks * 8 + 4 + tig];
            asm volatile(
                "mma.sync.aligned.m16n8k16.row.col.f32.f16.f16.f32 "
                "{%0,%1,%2,%3},{%4,%5,%6,%7},{%8,%9},{%0,%1,%2,%3};"
                : "+f"(c[nt][0]), "+f"(c[nt][1]), "+f"(c[nt][2]), "+f"(c[nt][3])
                : "r"(a0), "r"(a1), "r"(a2), "r"(a3), "r"(b0), "r"(b1));
        }
    }

    int gr0 = m0 + warp * 16 + g;
    int gr1 = gr0 + 8;
    float s1a = 0.f, s2a = 0.f, s1b = 0.f, s2b = 0.f;
#pragma unroll
    for (int nt = 0; nt < 8; nt++) {
        int lc = nt * 8 + tig * 2;
        int gc = n0 + lc;
        if (gr0 < M) store2(C + (size_t)gr0 * Nt + gc, c[nt][0], c[nt][1]);
        if (gr1 < M) store2(C + (size_t)gr1 * Nt + gc, c[nt][2], c[nt][3]);
        float a0 = asv[hd * 64 + lc], a1 = asv[hd * 64 + lc + 1];
        float d0 = adv[hd * 64 + lc], d1 = adv[hd * 64 + lc + 1];
        s1a += c[nt][0] * a0 + c[nt][1] * a1;
        s2a += c[nt][0] * d0 + c[nt][1] * d1;
        s1b += c[nt][2] * a0 + c[nt][3] * a1;
        s2b += c[nt][2] * d0 + c[nt][3] * d1;
    }
#pragma unroll
    for (int off = 1; off < 4; off <<= 1) {
        s1a += __shfl_xor_sync(0xffffffffu, s1a, off);
        s2a += __shfl_xor_sync(0xffffffffu, s2a, off);
        s1b += __shfl_xor_sync(0xffffffffu, s1b, off);
        s2b += __shfl_xor_sync(0xffffffffu, s2b, off);
    }
    if (tig == 0) {
        if (gr0 < M) { alsrc[(size_t)gr0 * H + hd] = s1a; aldst[(size_t)gr0 * H + hd] = s2a; }
        if (gr1 < M) { alsrc[(size_t)gr1 * H + hd] = s1b; aldst[(size_t)gr1 * H + hd] = s2b; }
    }
}

__device__ __forceinline__ float lrelu(float x) { return x > 0.f ? x : 0.2f * x; }

// ---------------- layer 1 aggregation + bias + LN(256) + ReLU --------------
__global__ __launch_bounds__(64) void k_agg1(const float* __restrict__ b1,
                                             const float* __restrict__ lng,
                                             const float* __restrict__ lnb) {
    int d = blockIdx.x;
    int t = threadIdx.x;
    int hd = t >> 4; // 4 heads x 16 threads
    __shared__ int s_src[64];
    __shared__ float s_w[64 * 4];
    __shared__ float rs[2], rq[2];
    __shared__ float s_ad[4];
    if (t < 4) s_ad[t] = g_aldst1[d * 4 + t];
    int beg = g_rowptr[d], end = g_rowptr[d + 1];
    float4 acc = make_float4(0.f, 0.f, 0.f, 0.f);
    float wsum = 0.f;
    for (int base = beg; base < end; base += 64) {
        int nE = min(64, end - base);
        if (t < nE) s_src[t] = g_esrc[base + t];
        __syncthreads();
        for (int idx = t; idx < nE * 4; idx += 64) {
            int e = idx >> 2, h2 = idx & 3;
            float v = g_alsrc1[s_src[e] * 4 + h2] + s_ad[h2];
            s_w[idx] = __expf(lrelu(v));
        }
        __syncthreads();
        int j = 0;
        for (; j + 4 <= nE; j += 4) {
            int s0 = s_src[j],     s1v = s_src[j + 1];
            int s2v = s_src[j + 2], s3v = s_src[j + 3];
            float w0 = s_w[(j + 0) * 4 + hd], w1 = s_w[(j + 1) * 4 + hd];
            float w2 = s_w[(j + 2) * 4 + hd], w3 = s_w[(j + 3) * 4 + hd];
            uint2 u0 = *reinterpret_cast<const uint2*>(g_h1 + (size_t)s0 * 256 + t * 4);
            uint2 u1 = *reinterpret_cast<const uint2*>(g_h1 + (size_t)s1v * 256 + t * 4);
            uint2 u2 = *reinterpret_cast<const uint2*>(g_h1 + (size_t)s2v * 256 + t * 4);
            uint2 u3 = *reinterpret_cast<const uint2*>(g_h1 + (size_t)s3v * 256 + t * 4);
            float2 a0 = __half22float2(*reinterpret_cast<__half2*>(&u0.x));
            float2 a1 = __half22float2(*reinterpret_cast<__half2*>(&u0.y));
            float2 b0 = __half22float2(*reinterpret_cast<__half2*>(&u1.x));
            float2 b1 = __half22float2(*reinterpret_cast<__half2*>(&u1.y));
            float2 c0 = __half22float2(*reinterpret_cast<__half2*>(&u2.x));
            float2 c1 = __half22float2(*reinterpret_cast<__half2*>(&u2.y));
            float2 d0 = __half22float2(*reinterpret_cast<__half2*>(&u3.x));
            float2 d1 = __half22float2(*reinterpret_cast<__half2*>(&u3.y));
            acc.x += w0 * a0.x + w1 * b0.x + w2 * c0.x + w3 * d0.x;
            acc.y += w0 * a0.y + w1 * b0.y + w2 * c0.y + w3 * d0.y;
            acc.z += w0 * a1.x + w1 * b1.x + w2 * c1.x + w3 * d1.x;
            acc.w += w0 * a1.y + w1 * b1.y + w2 * c1.y + w3 * d1.y;
            wsum += (w0 + w1) + (w2 + w3);
        }
        for (; j < nE; j++) {
            int s0 = s_src[j];
            float w0 = s_w[j * 4 + hd];
            uint2 u0 = *reinterpret_cast<const uint2*>(g_h1 + (size_t)s0 * 256 + t * 4);
            float2 a0 = __half22float2(*reinterpret_cast<__half2*>(&u0.x));
            float2 a1 = __half22float2(*reinterpret_cast<__half2*>(&u0.y));
            acc.x += w0 * a0.x; acc.y += w0 * a0.y;
            acc.z += w0 * a1.x; acc.w += w0 * a1.y;
            wsum += w0;
        }
        __syncthreads();
    }
    float inv = 1.f / wsum;
    float4 bv = *reinterpret_cast<const float4*>(b1 + t * 4);
    float4 o;
    o.x = acc.x * inv + bv.x; o.y = acc.y * inv + bv.y;
    o.z = acc.z * inv + bv.z; o.w = acc.w * inv + bv.w;
    float s = o.x + o.y + o.z + o.w;
    float q = o.x * o.x + o.y * o.y + o.z * o.z + o.w * o.w;
#pragma unroll
    for (int off = 16; off; off >>= 1) {
        s += __shfl_xor_sync(0xffffffffu, s, off);
        q += __shfl_xor_sync(0xffffffffu, q, off);
    }
    if ((t & 31) == 0) { rs[t >> 5] = s; rq[t >> 5] = q; }
    __syncthreads();
    float S = rs[0] + rs[1], Q = rq[0] + rq[1];
    float mu = S * (1.f / 256.f);
    float var = Q * (1.f / 256.f) - mu * mu;
    float rstd = rsqrtf(var + 1e-5f);
    float4 gv = *reinterpret_cast<const float4*>(lng + t * 4);
    float4 nbv = *reinterpret_cast<const float4*>(lnb + t * 4);
    o.x = fmaxf((o.x - mu) * rstd * gv.x + nbv.x, 0.f);
    o.y = fmaxf((o.y - mu) * rstd * gv.y + nbv.y, 0.f);
    o.z = fmaxf((o.z - mu) * rstd * gv.z + nbv.z, 0.f);
    o.w = fmaxf((o.w - mu) * rstd * gv.w + nbv.w, 0.f);
    *reinterpret_cast<float4*>(g_h1n + (size_t)d * 256 + t * 4) = o;
}

// ---------------- layer 2: 4 dst nodes per 64-thread block ------------------
__global__ __launch_bounds__(64) void k_agg2(const float* __restrict__ b2,
                                             const float* __restrict__ lng,
                                             const float* __restrict__ lnb,
                                             const float* __restrict__ f1W,
                                             const float* __restrict__ f1b,
                                             const float* __restrict__ f2W,
                                             const float* __restrict__ f2b,
                                             float* __restrict__ out, int N) {
    int t = threadIdx.x;
    int grp = t >> 4, tg = t & 15;
    int d = blockIdx.x * 4 + grp;
    __shared__ __align__(16) float hn[4][64];
    bool act = d < N;
    int beg = 0, end = 0;
    float ad2v = 0.f;
    if (act) { beg = g_rowptr[d]; end = g_rowptr[d + 1]; ad2v = g_aldst2[d]; }
    float4 acc = make_float4(0.f, 0.f, 0.f, 0.f);
    float wsum = 0.f;
    for (int j = beg; j < end; j++) {
        int s = g_esrc[j];
        float w = __expf(lrelu(g_alsrc2[s] + ad2v));
        uint2 u = *reinterpret_cast<const uint2*>(g_h2 + (size_t)s * 64 + tg * 4);
        float2 f0 = __half22float2(*reinterpret_cast<__half2*>(&u.x));
        float2 f1 = __half22float2(*reinterpret_cast<__half2*>(&u.y));
        acc.x += w * f0.x; acc.y += w * f0.y;
        acc.z += w * f1.x; acc.w += w * f1.y;
        wsum += w;
    }
    if (act) {
        float inv = 1.f / wsum;
        float4 bv = *reinterpret_cast<const float4*>(b2 + tg * 4);
        float4 o;
        o.x = acc.x * inv + bv.x; o.y = acc.y * inv + bv.y;
        o.z = acc.z * inv + bv.z; o.w = acc.w * inv + bv.w;
        float s = o.x + o.y + o.z + o.w;
        float q = o.x * o.x + o.y * o.y + o.z * o.z + o.w * o.w;
#pragma unroll
        for (int off = 8; off; off >>= 1) {
            s += __shfl_xor_sync(0xffffffffu, s, off, 16);
            q += __shfl_xor_sync(0xffffffffu, q, off, 16);
        }
        float mu = s * (1.f / 64.f);
        float var = q * (1.f / 64.f) - mu * mu;
        float rstd = rsqrtf(var + 1e-5f);
        float4 gv = *reinterpret_cast<const float4*>(lng + tg * 4);
        float4 nbv = *reinterpret_cast<const float4*>(lnb + tg * 4);
        float4 y;
        y.x = fmaxf((o.x - mu) * rstd * gv.x + nbv.x, 0.f);
        y.y = fmaxf((o.y - mu) * rstd * gv.y + nbv.y, 0.f);
        y.z = fmaxf((o.z - mu) * rstd * gv.z + nbv.z, 0.f);
        y.w = fmaxf((o.w - mu) * rstd * gv.w + nbv.w, 0.f);
        *reinterpret_cast<float4*>(&hn[grp][tg * 4]) = y;
    }
    __syncwarp();
    if (act) {
        float r0 = f1b[tg], r1 = f1b[tg + 16];
#pragma unroll
        for (int k = 0; k < 64; k++) {
            float h = hn[grp][k];
            r0 += h * f1W[k * 32 + tg];
            r1 += h * f1W[k * 32 + tg + 16];
        }
        float v = fmaxf(r0, 0.f) * f2W[tg] + fmaxf(r1, 0.f) * f2W[tg + 16];
#pragma unroll
        for (int off = 8; off; off >>= 1) v += __shfl_xor_sync(0xffffffffu, v, off, 16);
        if (tg == 0) out[d] = v + f2b[0];
    }
}

// ---------------- host launcher --------------------------------------------
extern "C" void kernel_launch(void* const* d_in, const int* in_sizes, int n_in,
                              void* d_out, int out_size) {
    const float* x       = (const float*)d_in[0];
    const void*  ei      = d_in[1];
    const float* W1      = (const float*)d_in[2];
    const float* as1     = (const float*)d_in[3];
    const float* ad1     = (const float*)d_in[4];
    const float* b1      = (const float*)d_in[5];
    const float* g1      = (const float*)d_in[6];
    const float* bb1     = (const float*)d_in[7];
    const float* W2      = (const float*)d_in[8];
    const float* as2     = (const float*)d_in[9];
    const float* ad2     = (const float*)d_in[10];
    const float* b2      = (const float*)d_in[11];
    const float* g2      = (const float*)d_in[12];
    const float* bb2     = (const float*)d_in[13];
    const float* f1W     = (const float*)d_in[14];
    const float* f1b     = (const float*)d_in[15];
    const float* f2W     = (const float*)d_in[16];
    const float* f2b     = (const float*)d_in[17];
    float* out = (float*)d_out;

    int N = in_sizes[0] / 128;
    int E = in_sizes[1] / 2;
    int ET = E + N;
    int nblk = (N + SCAN_TILE - 1) / SCAN_TILE;

    __half *h1p, *h2p;
    float *h1np, *als1p, *ald1p, *als2p, *ald2p;
    cudaGetSymbolAddress((void**)&h1p,   g_h1);
    cudaGetSymbolAddress((void**)&h1np,  g_h1n);
    cudaGetSymbolAddress((void**)&h2p,   g_h2);
    cudaGetSymbolAddress((void**)&als1p, g_alsrc1);
    cudaGetSymbolAddress((void**)&ald1p, g_aldst1);
    cudaGetSymbolAddress((void**)&als2p, g_alsrc2);
    cudaGetSymbolAddress((void**)&ald2p, g_aldst2);

    static int once = 0;
    static cudaStream_t s2;
    static cudaEvent_t evFork, evJoin;
    if (!once) {
        cudaFuncSetAttribute(k_gemm_mma<__half>,
                             cudaFuncAttributeMaxDynamicSharedMemorySize, 69632);
        cudaStreamCreateWithFlags(&s2, cudaStreamNonBlocking);
        cudaEventCreateWithFlags(&evFork, cudaEventDisableTiming);
        cudaEventCreateWithFlags(&evJoin, cudaEventDisableTiming);
        once = 1;
    }
    int smem1 = 2 * 64 * (128 + 8) * (int)sizeof(__half); // 34,816
    int smem2 = 2 * 64 * (256 + 8) * (int)sizeof(__half); // 67,584

    // ---- fork: CSR build on s2, GEMM1 on main stream --------------------
    cudaEventRecord(evFork, 0);
    cudaStreamWaitEvent(s2, evFork, 0);

    k_init   <<<(N + 255) / 256, 256, 0, s2>>>(ei, N);
    k_count  <<<(ET + 255) / 256, 256, 0, s2>>>(ei, E, N);
    k_scan1  <<<nblk, 256, 0, s2>>>(N);
    k_scan3  <<<nblk, 256, 0, s2>>>(N, nblk);
    k_scatter<<<(ET + 255) / 256, 256, 0, s2>>>(ei, E, N);
    cudaEventRecord(evJoin, s2);

    // Layer 1 GEMM (+ fused attention logits) runs concurrently
    k_gemm_mma<__half><<<dim3((N + 63) / 64, 4), 128, smem1>>>(
        x, W1, h1p, as1, ad1, als1p, ald1p, N, 256, 128, 4);

    // ---- join: agg1 needs both CSR and GEMM1 ----------------------------
    cudaStreamWaitEvent(0, evJoin, 0);
    k_agg1<<<N, 64>>>(b1, g1, bb1);

    // Layer 2
    k_gemm_mma<__half><<<dim3((N + 63) / 64, 1), 128, smem2>>>(
        h1np, W2, h2p, as2, ad2, als2p, ald2p, N, 64, 256, 1);
    k_agg2<<<(N + 3) / 4, 64>>>(b2, g2, bb2, f1W, f1b, f2W, f2b, out, N);

    (void)n_in; (void)out_size;
}